// round 1
// baseline (speedup 1.0000x reference)
#include <cuda_runtime.h>
#include <math.h>

#define Bsz 2
#define Tt 2048
#define Dd 2048
#define Hh 16
#define KVh 4
#define HD 128
#define GQ (Hh/KVh)

// Scratch (allocation-free rule: __device__ globals)
__device__ float g_q[(size_t)Bsz*Tt*Dd];          // [B,T,H,HD]
__device__ float g_k[(size_t)Bsz*Tt*KVh*HD];      // [B,T,KV,HD]
__device__ float g_v[(size_t)Bsz*Tt*KVh*HD];      // [B,T,KV,HD]
__device__ float g_o[(size_t)Bsz*Tt*Dd];          // [B,T,H,HD]

// ---------------- SGEMM: C[M,N] = A[M,K] @ B[K,N], fp32 ----------------
// 128x128 block, K-step 8, 256 threads, 8x8 per-thread microtile.
__global__ void __launch_bounds__(256) sgemm_kernel(
    const float* __restrict__ A, const float* __restrict__ B,
    float* __restrict__ C, int M, int N, int K)
{
    __shared__ float As[8][128];
    __shared__ float Bs[8][128];
    int tid = threadIdx.x;
    int tx = tid & 15, ty = tid >> 4;
    int m0 = blockIdx.y * 128, n0 = blockIdx.x * 128;

    float acc[8][8];
#pragma unroll
    for (int i = 0; i < 8; i++)
#pragma unroll
        for (int j = 0; j < 8; j++) acc[i][j] = 0.f;

    int arow = tid >> 1;           // 0..127
    int acol = (tid & 1) * 4;      // 0 or 4
    int brow = tid >> 5;           // 0..7
    int bcol = (tid & 31) * 4;     // 0..124
    const float* Ap = A + (size_t)(m0 + arow) * K + acol;
    const float* Bp = B + (size_t)brow * N + n0 + bcol;

    for (int k0 = 0; k0 < K; k0 += 8) {
        float4 a = *(const float4*)(Ap + k0);
        float4 b = *(const float4*)(Bp + (size_t)k0 * N);
        As[acol + 0][arow] = a.x;
        As[acol + 1][arow] = a.y;
        As[acol + 2][arow] = a.z;
        As[acol + 3][arow] = a.w;
        *(float4*)&Bs[brow][bcol] = b;
        __syncthreads();
#pragma unroll
        for (int k = 0; k < 8; k++) {
            float av[8], bv[8];
            *(float4*)&av[0] = *(const float4*)&As[k][ty * 8];
            *(float4*)&av[4] = *(const float4*)&As[k][ty * 8 + 4];
            *(float4*)&bv[0] = *(const float4*)&Bs[k][tx * 8];
            *(float4*)&bv[4] = *(const float4*)&Bs[k][tx * 8 + 4];
#pragma unroll
            for (int i = 0; i < 8; i++)
#pragma unroll
                for (int j = 0; j < 8; j++)
                    acc[i][j] = fmaf(av[i], bv[j], acc[i][j]);
        }
        __syncthreads();
    }
#pragma unroll
    for (int i = 0; i < 8; i++) {
        float* Cp = C + (size_t)(m0 + ty * 8 + i) * N + n0 + tx * 8;
        *(float4*)Cp       = make_float4(acc[i][0], acc[i][1], acc[i][2], acc[i][3]);
        *(float4*)(Cp + 4) = make_float4(acc[i][4], acc[i][5], acc[i][6], acc[i][7]);
    }
}

// ---------------- RoPE (in place, reference split-halves layout) ----------------
// buf rows of HD=128 floats; row = (b*T + t)*nh + h. 128 threads handle 2 rows.
__global__ void rope_kernel(float* __restrict__ buf, int nh)
{
    int row = blockIdx.x * 2 + (threadIdx.x >> 6);
    int f = threadIdx.x & 63;
    float* r = buf + (size_t)row * HD;
    float x1 = r[2 * f];
    float x2 = r[2 * f + 1];
    int t = (row / nh) % Tt;
    float inv = 1.0f / powf(10000.0f, (float)f * (1.0f / 64.0f));
    float ang = (float)t * inv;
    float s, c;
    sincosf(ang, &s, &c);
    __syncthreads();   // all reads of both rows complete before any writes
    r[f]      = x1 * c - x2 * s;
    r[64 + f] = x1 * s + x2 * c;
}

// ---------------- Flash attention (causal, GQA), fp32 ----------------
#define FBQ 64
#define FBK 64
#define SSTR 65

__global__ void __launch_bounds__(256) flash_kernel(
    const float* __restrict__ Q, const float* __restrict__ K,
    const float* __restrict__ V, float* __restrict__ O)
{
    extern __shared__ float sm[];
    float* Qs = sm;                        // FBQ*HD
    float* Ks = Qs + FBQ * HD;             // FBK*HD
    float* Vs = Ks + FBK * HD;             // FBK*HD
    float* Ss = Vs + FBK * HD;             // FBQ*SSTR
    float* mrow = Ss + FBQ * SSTR;         // FBQ
    float* lrow = mrow + FBQ;              // FBQ
    float* arow = lrow + FBQ;              // FBQ

    int q0 = blockIdx.x * FBQ;
    int h  = blockIdx.y;
    int b  = blockIdx.z;
    int kvh = h / GQ;
    int tid = threadIdx.x;
    int tx = tid & 15, ty = tid >> 4;

    const float scale = 0.08838834764831845f;  // 1/sqrt(128)

    // Load Q tile (pre-scaled)
    const float* Qg = Q + (((size_t)b * Tt + q0) * Hh + h) * HD;
#pragma unroll
    for (int i = 0; i < 8; i++) {
        int idx = tid + i * 256;               // float4 index, 0..2047
        int r = idx >> 5, d4 = idx & 31;
        float4 v = *(const float4*)(Qg + (size_t)r * Hh * HD + d4 * 4);
        v.x *= scale; v.y *= scale; v.z *= scale; v.w *= scale;
        *(float4*)&Qs[r * HD + d4 * 4] = v;
    }
    if (tid < FBQ) { mrow[tid] = -1e30f; lrow[tid] = 0.f; }

    float acc[4][8];
#pragma unroll
    for (int i = 0; i < 4; i++)
#pragma unroll
        for (int j = 0; j < 8; j++) acc[i][j] = 0.f;

    int ntiles = q0 / FBK + 1;
    for (int j = 0; j < ntiles; j++) {
        __syncthreads();   // protect Ss/Ks/Vs from previous iter (and Qs/mrow on iter 0)
        const float* Kg = K + (((size_t)b * Tt + j * FBK) * KVh + kvh) * HD;
        const float* Vg = V + (((size_t)b * Tt + j * FBK) * KVh + kvh) * HD;
#pragma unroll
        for (int i = 0; i < 8; i++) {
            int idx = tid + i * 256;
            int r = idx >> 5, d4 = idx & 31;
            *(float4*)&Ks[r * HD + d4 * 4] = *(const float4*)(Kg + (size_t)r * KVh * HD + d4 * 4);
            *(float4*)&Vs[r * HD + d4 * 4] = *(const float4*)(Vg + (size_t)r * KVh * HD + d4 * 4);
        }
        __syncthreads();

        // S = Qs @ Ks^T: thread computes rows ty*4..+3, cols tx*4..+3
        float s[4][4];
#pragma unroll
        for (int i = 0; i < 4; i++)
#pragma unroll
            for (int jj = 0; jj < 4; jj++) s[i][jj] = 0.f;

        for (int d = 0; d < HD; d += 4) {
            float4 qv[4], kv[4];
#pragma unroll
            for (int i = 0; i < 4; i++) qv[i] = *(const float4*)&Qs[(ty * 4 + i) * HD + d];
#pragma unroll
            for (int i = 0; i < 4; i++) kv[i] = *(const float4*)&Ks[(tx * 4 + i) * HD + d];
#pragma unroll
            for (int i = 0; i < 4; i++)
#pragma unroll
                for (int jj = 0; jj < 4; jj++) {
                    s[i][jj] = fmaf(qv[i].x, kv[jj].x, s[i][jj]);
                    s[i][jj] = fmaf(qv[i].y, kv[jj].y, s[i][jj]);
                    s[i][jj] = fmaf(qv[i].z, kv[jj].z, s[i][jj]);
                    s[i][jj] = fmaf(qv[i].w, kv[jj].w, s[i][jj]);
                }
        }
        bool diag = (j == ntiles - 1);
#pragma unroll
        for (int i = 0; i < 4; i++)
#pragma unroll
            for (int jj = 0; jj < 4; jj++) {
                if (diag && (j * FBK + tx * 4 + jj > q0 + ty * 4 + i)) s[i][jj] = -1e30f;
                Ss[(ty * 4 + i) * SSTR + tx * 4 + jj] = s[i][jj];
            }
        __syncthreads();

        // Online softmax: one thread per query row
        if (tid < FBQ) {
            int r = tid;
            float mold = mrow[r], mnew = mold;
            for (int k = 0; k < FBK; k++) mnew = fmaxf(mnew, Ss[r * SSTR + k]);
            float alpha = __expf(mold - mnew);
            float sum = 0.f;
            for (int k = 0; k < FBK; k++) {
                float p = __expf(Ss[r * SSTR + k] - mnew);
                Ss[r * SSTR + k] = p;
                sum += p;
            }
            lrow[r] = lrow[r] * alpha + sum;
            mrow[r] = mnew;
            arow[r] = alpha;
        }
        __syncthreads();

        // Rescale accumulators, then O += P @ V
        float al[4];
#pragma unroll
        for (int i = 0; i < 4; i++) al[i] = arow[ty * 4 + i];
#pragma unroll
        for (int i = 0; i < 4; i++)
#pragma unroll
            for (int c = 0; c < 8; c++) acc[i][c] *= al[i];

        for (int k = 0; k < FBK; k++) {
            float p[4];
#pragma unroll
            for (int i = 0; i < 4; i++) p[i] = Ss[(ty * 4 + i) * SSTR + k];
            float4 v0 = *(const float4*)&Vs[k * HD + tx * 8];
            float4 v1 = *(const float4*)&Vs[k * HD + tx * 8 + 4];
#pragma unroll
            for (int i = 0; i < 4; i++) {
                acc[i][0] = fmaf(p[i], v0.x, acc[i][0]);
                acc[i][1] = fmaf(p[i], v0.y, acc[i][1]);
                acc[i][2] = fmaf(p[i], v0.z, acc[i][2]);
                acc[i][3] = fmaf(p[i], v0.w, acc[i][3]);
                acc[i][4] = fmaf(p[i], v1.x, acc[i][4]);
                acc[i][5] = fmaf(p[i], v1.y, acc[i][5]);
                acc[i][6] = fmaf(p[i], v1.z, acc[i][6]);
                acc[i][7] = fmaf(p[i], v1.w, acc[i][7]);
            }
        }
    }

    // Epilogue: normalize and write O in [B,T,H,HD]
#pragma unroll
    for (int i = 0; i < 4; i++) {
        float inv_l = 1.0f / lrow[ty * 4 + i];
        float* Op = O + (((size_t)b * Tt + q0 + ty * 4 + i) * Hh + h) * HD + tx * 8;
        *(float4*)Op       = make_float4(acc[i][0] * inv_l, acc[i][1] * inv_l,
                                         acc[i][2] * inv_l, acc[i][3] * inv_l);
        *(float4*)(Op + 4) = make_float4(acc[i][4] * inv_l, acc[i][5] * inv_l,
                                         acc[i][6] * inv_l, acc[i][7] * inv_l);
    }
}

// ---------------- launch ----------------
extern "C" void kernel_launch(void* const* d_in, const int* in_sizes, int n_in,
                              void* d_out, int out_size)
{
    const float* x  = (const float*)d_in[0];
    const float* Wq = (const float*)d_in[1];
    const float* Wk = (const float*)d_in[2];
    const float* Wv = (const float*)d_in[3];
    const float* Wo = (const float*)d_in[4];
    float* out = (float*)d_out;

    float *q, *k, *v, *o;
    cudaGetSymbolAddress((void**)&q, g_q);
    cudaGetSymbolAddress((void**)&k, g_k);
    cudaGetSymbolAddress((void**)&v, g_v);
    cudaGetSymbolAddress((void**)&o, g_o);

    const int M = Bsz * Tt;   // 4096
    dim3 blk(256);

    // Projections
    sgemm_kernel<<<dim3(Dd / 128, M / 128), blk>>>(x, Wq, q, M, Dd, Dd);
    sgemm_kernel<<<dim3((KVh * HD) / 128, M / 128), blk>>>(x, Wk, k, M, KVh * HD, Dd);
    sgemm_kernel<<<dim3((KVh * HD) / 128, M / 128), blk>>>(x, Wv, v, M, KVh * HD, Dd);

    // RoPE on q and k
    rope_kernel<<<(Bsz * Tt * Hh) / 2, 128>>>(q, Hh);
    rope_kernel<<<(Bsz * Tt * KVh) / 2, 128>>>(k, KVh);

    // Flash attention
    int smem = (3 * FBQ * HD + FBQ * SSTR + 3 * FBQ) * (int)sizeof(float);
    cudaFuncSetAttribute(flash_kernel, cudaFuncAttributeMaxDynamicSharedMemorySize, smem);
    flash_kernel<<<dim3(Tt / FBQ, Hh, Bsz), blk, smem>>>(q, k, v, o);

    // Output projection -> d_out
    sgemm_kernel<<<dim3(Dd / 128, M / 128), blk>>>(o, Wo, out, M, Dd, Dd);
}

// round 3
// speedup vs baseline: 1.4070x; 1.4070x over previous
#include <cuda_runtime.h>
#include <cuda_bf16.h>
#include <cstdint>
#include <math.h>

#define Bsz 2
#define Tt 2048
#define Dd 2048
#define Hh 16
#define KVh 4
#define HD 128
#define GQ (Hh/KVh)

// ---------------- scratch (__device__ globals; no allocation allowed) ----------------
__device__ float g_q[(size_t)Bsz*Tt*Dd];
__device__ float g_k[(size_t)Bsz*Tt*KVh*HD];
__device__ float g_v[(size_t)Bsz*Tt*KVh*HD];
__device__ float g_o[(size_t)Bsz*Tt*Dd];

__device__ __nv_bfloat16 g_xs_h[(size_t)Bsz*Tt*Dd];
__device__ __nv_bfloat16 g_xs_l[(size_t)Bsz*Tt*Dd];
__device__ __nv_bfloat16 g_os_h[(size_t)Bsz*Tt*Dd];
__device__ __nv_bfloat16 g_os_l[(size_t)Bsz*Tt*Dd];
__device__ __nv_bfloat16 g_wqt_h[(size_t)Dd*Dd];
__device__ __nv_bfloat16 g_wqt_l[(size_t)Dd*Dd];
__device__ __nv_bfloat16 g_wkt_h[(size_t)KVh*HD*Dd];
__device__ __nv_bfloat16 g_wkt_l[(size_t)KVh*HD*Dd];
__device__ __nv_bfloat16 g_wvt_h[(size_t)KVh*HD*Dd];
__device__ __nv_bfloat16 g_wvt_l[(size_t)KVh*HD*Dd];
__device__ __nv_bfloat16 g_wot_h[(size_t)Dd*Dd];
__device__ __nv_bfloat16 g_wot_l[(size_t)Dd*Dd];

// ---------------- helpers ----------------
__device__ __forceinline__ uint32_t smem_u32(const void* p) {
    uint32_t a;
    asm("{ .reg .u64 t; cvta.to.shared.u64 t, %1; cvt.u32.u64 %0, t; }" : "=r"(a) : "l"(p));
    return a;
}

#define CP_ASYNC16(dst, src) \
    asm volatile("cp.async.cg.shared.global [%0], [%1], 16;" :: "r"(dst), "l"(src))
#define CP_COMMIT() asm volatile("cp.async.commit_group;")
#define CP_WAIT1()  asm volatile("cp.async.wait_group 1;")

#define LDSM_X4(r0, r1, r2, r3, addr) \
    asm volatile("ldmatrix.sync.aligned.m8n8.x4.shared.b16 {%0,%1,%2,%3}, [%4];" \
        : "=r"(r0), "=r"(r1), "=r"(r2), "=r"(r3) : "r"(addr))

#define MMA16816(c, a, b0, b1) \
    asm volatile("mma.sync.aligned.m16n8k16.row.col.f32.bf16.bf16.f32 " \
        "{%0,%1,%2,%3},{%4,%5,%6,%7},{%8,%9},{%0,%1,%2,%3};" \
        : "+f"((c)[0]), "+f"((c)[1]), "+f"((c)[2]), "+f"((c)[3]) \
        : "r"((a)[0]), "r"((a)[1]), "r"((a)[2]), "r"((a)[3]), "r"(b0), "r"(b1))

// ---------------- conversion kernels ----------------
__global__ void split_kernel(const float* __restrict__ A,
                             __nv_bfloat16* __restrict__ H,
                             __nv_bfloat16* __restrict__ L, int n4)
{
    int i = blockIdx.x * blockDim.x + threadIdx.x;
    int stride = gridDim.x * blockDim.x;
    for (; i < n4; i += stride) {
        float4 a = ((const float4*)A)[i];
        __nv_bfloat16 h0 = __float2bfloat16(a.x);
        __nv_bfloat16 h1 = __float2bfloat16(a.y);
        __nv_bfloat16 h2 = __float2bfloat16(a.z);
        __nv_bfloat16 h3 = __float2bfloat16(a.w);
        __nv_bfloat16 l0 = __float2bfloat16(a.x - __bfloat162float(h0));
        __nv_bfloat16 l1 = __float2bfloat16(a.y - __bfloat162float(h1));
        __nv_bfloat16 l2 = __float2bfloat16(a.z - __bfloat162float(h2));
        __nv_bfloat16 l3 = __float2bfloat16(a.w - __bfloat162float(h3));
        ((__nv_bfloat162*)H)[2*i]   = __nv_bfloat162(h0, h1);
        ((__nv_bfloat162*)H)[2*i+1] = __nv_bfloat162(h2, h3);
        ((__nv_bfloat162*)L)[2*i]   = __nv_bfloat162(l0, l1);
        ((__nv_bfloat162*)L)[2*i+1] = __nv_bfloat162(l2, l3);
    }
}

// W[K,N] fp32 -> Wt_hi/lo[N,K] bf16 (transpose + split)
__global__ void tsplit_kernel(const float* __restrict__ W,
                              __nv_bfloat16* __restrict__ Th,
                              __nv_bfloat16* __restrict__ Tl, int K, int N)
{
    __shared__ float t[32][33];
    int n0 = blockIdx.x * 32, k0 = blockIdx.y * 32;
    int tx = threadIdx.x, ty0 = threadIdx.y;
#pragma unroll
    for (int j = 0; j < 4; j++) {
        int ty = ty0 + j * 8;
        t[ty][tx] = W[(size_t)(k0 + ty) * N + n0 + tx];
    }
    __syncthreads();
#pragma unroll
    for (int j = 0; j < 4; j++) {
        int ty = ty0 + j * 8;
        float v = t[tx][ty];
        size_t o = (size_t)(n0 + ty) * K + k0 + tx;
        __nv_bfloat16 h = __float2bfloat16(v);
        Th[o] = h;
        Tl[o] = __float2bfloat16(v - __bfloat162float(h));
    }
}

// ---------------- mma.sync bf16x3 GEMM: C[M,N] = A[M,K] @ Bt[N,K]^T ----------------
// 128x128 CTA tile, 8 warps (2x4), warp tile 64x32, K-stage 32, 3-stage cp.async.
#define KSP 40                       // halves per smem row (80B stride, conflict-free)
#define TILE_B (128 * KSP * 2)       // 10240 bytes per tile
#define STAGE_B (4 * TILE_B)         // Ah, Al, Bh, Bl
#define NSTG 3
#define GEMM_SMEM (NSTG * STAGE_B)   // 122880

__global__ void __launch_bounds__(256, 1) mma_gemm(
    const __nv_bfloat16* __restrict__ Ah, const __nv_bfloat16* __restrict__ Al,
    const __nv_bfloat16* __restrict__ Bh, const __nv_bfloat16* __restrict__ Bl,
    float* __restrict__ C, int M, int N, int K)
{
    extern __shared__ char sm[];
    uint32_t smem_base = smem_u32(sm);
    int tid = threadIdx.x;
    int wid = tid >> 5, lane = tid & 31;
    int wm = wid >> 2, wn = wid & 3;      // 2 x 4 warp grid

    int m0 = blockIdx.y * 128, n0 = blockIdx.x * 128;
    int nstage = K / 32;

    float acc[4][4][4];
#pragma unroll
    for (int a = 0; a < 4; a++)
#pragma unroll
        for (int b = 0; b < 4; b++)
#pragma unroll
            for (int c = 0; c < 4; c++) acc[a][b][c] = 0.f;

    // ---- async load of one stage: 2048 16B chunks, 8 per thread ----
    auto load_stage = [&](int kc, int s) {
        int kcol = kc * 32;
        uint32_t sb = smem_base + s * STAGE_B;
#pragma unroll
        for (int i = 0; i < 8; i++) {
            int c = tid + i * 256;
            int tile = c >> 9;           // 0..3
            int cid = c & 511;
            int row = cid >> 2;
            int kch = cid & 3;
            const __nv_bfloat16* src;
            if (tile == 0)      src = Ah + (size_t)(m0 + row) * K + kcol + kch * 8;
            else if (tile == 1) src = Al + (size_t)(m0 + row) * K + kcol + kch * 8;
            else if (tile == 2) src = Bh + (size_t)(n0 + row) * K + kcol + kch * 8;
            else                src = Bl + (size_t)(n0 + row) * K + kcol + kch * 8;
            uint32_t dst = sb + tile * TILE_B + (row * KSP + kch * 8) * 2;
            CP_ASYNC16(dst, src);
        }
    };

    load_stage(0, 0); CP_COMMIT();
    load_stage(1, 1); CP_COMMIT();

    // per-warp ldmatrix base offsets (within a tile, bytes)
    uint32_t aoff = ((wm * 64 + (lane & 15)) * KSP + ((lane >> 4) << 3)) * 2;
    uint32_t boff = ((wn * 32 + ((lane >> 4) << 3) + (lane & 7)) * KSP + (((lane >> 3) & 1) << 3)) * 2;

    for (int kc = 0; kc < nstage; kc++) {
        CP_WAIT1();
        __syncthreads();
        if (kc + 2 < nstage) load_stage(kc + 2, (kc + 2) % NSTG);
        CP_COMMIT();

        uint32_t sb = smem_base + (kc % NSTG) * STAGE_B;
        uint32_t aHi = sb + aoff;
        uint32_t aLo = aHi + TILE_B;
        uint32_t bHi = sb + 2 * TILE_B + boff;
        uint32_t bLo = bHi + TILE_B;

#pragma unroll
        for (int kk = 0; kk < 2; kk++) {
            uint32_t ko = kk * 32;   // 16 halves
            uint32_t ah[4][4], al[4][4], bh[2][4], bl[2][4];
#pragma unroll
            for (int mt = 0; mt < 4; mt++) {
                LDSM_X4(ah[mt][0], ah[mt][1], ah[mt][2], ah[mt][3], aHi + mt * 16 * KSP * 2 + ko);
                LDSM_X4(al[mt][0], al[mt][1], al[mt][2], al[mt][3], aLo + mt * 16 * KSP * 2 + ko);
            }
#pragma unroll
            for (int pr = 0; pr < 2; pr++) {
                LDSM_X4(bh[pr][0], bh[pr][1], bh[pr][2], bh[pr][3], bHi + pr * 16 * KSP * 2 + ko);
                LDSM_X4(bl[pr][0], bl[pr][1], bl[pr][2], bl[pr][3], bLo + pr * 16 * KSP * 2 + ko);
            }
#pragma unroll
            for (int mt = 0; mt < 4; mt++)
#pragma unroll
                for (int nt = 0; nt < 4; nt++) {
                    int pr = nt >> 1, ix = (nt & 1) * 2;
                    MMA16816(acc[mt][nt], ah[mt], bh[pr][ix], bh[pr][ix + 1]);
                    MMA16816(acc[mt][nt], ah[mt], bl[pr][ix], bl[pr][ix + 1]);
                    MMA16816(acc[mt][nt], al[mt], bh[pr][ix], bh[pr][ix + 1]);
                }
        }
    }

    // epilogue
#pragma unroll
    for (int mt = 0; mt < 4; mt++)
#pragma unroll
        for (int nt = 0; nt < 4; nt++) {
            int row = m0 + wm * 64 + mt * 16 + (lane >> 2);
            int col = n0 + wn * 32 + nt * 8 + (lane & 3) * 2;
            *(float2*)&C[(size_t)row * N + col]       = make_float2(acc[mt][nt][0], acc[mt][nt][1]);
            *(float2*)&C[(size_t)(row + 8) * N + col] = make_float2(acc[mt][nt][2], acc[mt][nt][3]);
        }
}

// ---------------- RoPE ----------------
__global__ void rope_kernel(float* __restrict__ buf, int nh)
{
    int row = blockIdx.x * 2 + (threadIdx.x >> 6);
    int f = threadIdx.x & 63;
    float* r = buf + (size_t)row * HD;
    float x1 = r[2 * f];
    float x2 = r[2 * f + 1];
    int t = (row / nh) % Tt;
    float inv = 1.0f / powf(10000.0f, (float)f * (1.0f / 64.0f));
    float ang = (float)t * inv;
    float s, c;
    sincosf(ang, &s, &c);
    __syncthreads();
    r[f]      = x1 * c - x2 * s;
    r[64 + f] = x1 * s + x2 * c;
}

// ---------------- Flash attention fp32 (parallel softmax) ----------------
#define FBQ 64
#define FBK 64
#define SSTR 65

__global__ void __launch_bounds__(256) flash_kernel(
    const float* __restrict__ Q, const float* __restrict__ K,
    const float* __restrict__ V, float* __restrict__ O)
{
    extern __shared__ float smf[];
    float* Qs = smf;
    float* Ks = Qs + FBQ * HD;
    float* Vs = Ks + FBK * HD;
    float* Ss = Vs + FBK * HD;
    float* mrow = Ss + FBQ * SSTR;
    float* lrow = mrow + FBQ;
    float* arow = lrow + FBQ;

    int q0 = blockIdx.x * FBQ;
    int h  = blockIdx.y;
    int b  = blockIdx.z;
    int kvh = h / GQ;
    int tid = threadIdx.x;
    int tx = tid & 15, ty = tid >> 4;

    const float scale = 0.08838834764831845f;

    const float* Qg = Q + (((size_t)b * Tt + q0) * Hh + h) * HD;
#pragma unroll
    for (int i = 0; i < 8; i++) {
        int idx = tid + i * 256;
        int r = idx >> 5, d4 = idx & 31;
        float4 v = *(const float4*)(Qg + (size_t)r * Hh * HD + d4 * 4);
        v.x *= scale; v.y *= scale; v.z *= scale; v.w *= scale;
        *(float4*)&Qs[r * HD + d4 * 4] = v;
    }
    if (tid < FBQ) { mrow[tid] = -1e30f; lrow[tid] = 0.f; }

    float acc[4][8];
#pragma unroll
    for (int i = 0; i < 4; i++)
#pragma unroll
        for (int j = 0; j < 8; j++) acc[i][j] = 0.f;

    int ntiles = q0 / FBK + 1;
    for (int j = 0; j < ntiles; j++) {
        __syncthreads();
        const float* Kg = K + (((size_t)b * Tt + j * FBK) * KVh + kvh) * HD;
        const float* Vg = V + (((size_t)b * Tt + j * FBK) * KVh + kvh) * HD;
#pragma unroll
        for (int i = 0; i < 8; i++) {
            int idx = tid + i * 256;
            int r = idx >> 5, d4 = idx & 31;
            *(float4*)&Ks[r * HD + d4 * 4] = *(const float4*)(Kg + (size_t)r * KVh * HD + d4 * 4);
            *(float4*)&Vs[r * HD + d4 * 4] = *(const float4*)(Vg + (size_t)r * KVh * HD + d4 * 4);
        }
        __syncthreads();

        float s[4][4];
#pragma unroll
        for (int i = 0; i < 4; i++)
#pragma unroll
            for (int jj = 0; jj < 4; jj++) s[i][jj] = 0.f;

        for (int d = 0; d < HD; d += 4) {
            float4 qv[4], kv[4];
#pragma unroll
            for (int i = 0; i < 4; i++) qv[i] = *(const float4*)&Qs[(ty * 4 + i) * HD + d];
#pragma unroll
            for (int i = 0; i < 4; i++) kv[i] = *(const float4*)&Ks[(tx * 4 + i) * HD + d];
#pragma unroll
            for (int i = 0; i < 4; i++)
#pragma unroll
                for (int jj = 0; jj < 4; jj++) {
                    s[i][jj] = fmaf(qv[i].x, kv[jj].x, s[i][jj]);
                    s[i][jj] = fmaf(qv[i].y, kv[jj].y, s[i][jj]);
                    s[i][jj] = fmaf(qv[i].z, kv[jj].z, s[i][jj]);
                    s[i][jj] = fmaf(qv[i].w, kv[jj].w, s[i][jj]);
                }
        }
        bool diag = (j == ntiles - 1);
#pragma unroll
        for (int i = 0; i < 4; i++)
#pragma unroll
            for (int jj = 0; jj < 4; jj++) {
                if (diag && (j * FBK + tx * 4 + jj > q0 + ty * 4 + i)) s[i][jj] = -1e30f;
                Ss[(ty * 4 + i) * SSTR + tx * 4 + jj] = s[i][jj];
            }
        __syncthreads();

        // online softmax: 4 threads per row + shfl reduce
        {
            int r = tid >> 2, sub = tid & 3;
            int kb = sub * 16;
            float mloc = -1e30f;
#pragma unroll
            for (int k = 0; k < 16; k++) mloc = fmaxf(mloc, Ss[r * SSTR + kb + k]);
            mloc = fmaxf(mloc, __shfl_xor_sync(0xffffffff, mloc, 1));
            mloc = fmaxf(mloc, __shfl_xor_sync(0xffffffff, mloc, 2));
            float mold = mrow[r];
            float mnew = fmaxf(mold, mloc);
            float sum = 0.f;
#pragma unroll
            for (int k = 0; k < 16; k++) {
                float p = __expf(Ss[r * SSTR + kb + k] - mnew);
                Ss[r * SSTR + kb + k] = p;
                sum += p;
            }
            sum += __shfl_xor_sync(0xffffffff, sum, 1);
            sum += __shfl_xor_sync(0xffffffff, sum, 2);
            if (sub == 0) {
                float alpha = __expf(mold - mnew);
                lrow[r] = lrow[r] * alpha + sum;
                mrow[r] = mnew;
                arow[r] = alpha;
            }
        }
        __syncthreads();

        float al[4];
#pragma unroll
        for (int i = 0; i < 4; i++) al[i] = arow[ty * 4 + i];
#pragma unroll
        for (int i = 0; i < 4; i++)
#pragma unroll
            for (int c = 0; c < 8; c++) acc[i][c] *= al[i];

        for (int k = 0; k < FBK; k++) {
            float p[4];
#pragma unroll
            for (int i = 0; i < 4; i++) p[i] = Ss[(ty * 4 + i) * SSTR + k];
            float4 v0 = *(const float4*)&Vs[k * HD + tx * 8];
            float4 v1 = *(const float4*)&Vs[k * HD + tx * 8 + 4];
#pragma unroll
            for (int i = 0; i < 4; i++) {
                acc[i][0] = fmaf(p[i], v0.x, acc[i][0]);
                acc[i][1] = fmaf(p[i], v0.y, acc[i][1]);
                acc[i][2] = fmaf(p[i], v0.z, acc[i][2]);
                acc[i][3] = fmaf(p[i], v0.w, acc[i][3]);
                acc[i][4] = fmaf(p[i], v1.x, acc[i][4]);
                acc[i][5] = fmaf(p[i], v1.y, acc[i][5]);
                acc[i][6] = fmaf(p[i], v1.z, acc[i][6]);
                acc[i][7] = fmaf(p[i], v1.w, acc[i][7]);
            }
        }
    }

#pragma unroll
    for (int i = 0; i < 4; i++) {
        float inv_l = 1.0f / lrow[ty * 4 + i];
        float* Op = O + (((size_t)b * Tt + q0 + ty * 4 + i) * Hh + h) * HD + tx * 8;
        *(float4*)Op       = make_float4(acc[i][0] * inv_l, acc[i][1] * inv_l,
                                         acc[i][2] * inv_l, acc[i][3] * inv_l);
        *(float4*)(Op + 4) = make_float4(acc[i][4] * inv_l, acc[i][5] * inv_l,
                                         acc[i][6] * inv_l, acc[i][7] * inv_l);
    }
}

// ---------------- launch ----------------
extern "C" void kernel_launch(void* const* d_in, const int* in_sizes, int n_in,
                              void* d_out, int out_size)
{
    const float* x  = (const float*)d_in[0];
    const float* Wq = (const float*)d_in[1];
    const float* Wk = (const float*)d_in[2];
    const float* Wv = (const float*)d_in[3];
    const float* Wo = (const float*)d_in[4];
    float* out = (float*)d_out;

    float *q, *k, *v, *o;
    cudaGetSymbolAddress((void**)&q, g_q);
    cudaGetSymbolAddress((void**)&k, g_k);
    cudaGetSymbolAddress((void**)&v, g_v);
    cudaGetSymbolAddress((void**)&o, g_o);
    __nv_bfloat16 *xsh, *xsl, *osh, *osl;
    __nv_bfloat16 *wqh, *wql, *wkh, *wkl, *wvh, *wvl, *woh, *wol;
    cudaGetSymbolAddress((void**)&xsh, g_xs_h);
    cudaGetSymbolAddress((void**)&xsl, g_xs_l);
    cudaGetSymbolAddress((void**)&osh, g_os_h);
    cudaGetSymbolAddress((void**)&osl, g_os_l);
    cudaGetSymbolAddress((void**)&wqh, g_wqt_h);
    cudaGetSymbolAddress((void**)&wql, g_wqt_l);
    cudaGetSymbolAddress((void**)&wkh, g_wkt_h);
    cudaGetSymbolAddress((void**)&wkl, g_wkt_l);
    cudaGetSymbolAddress((void**)&wvh, g_wvt_h);
    cudaGetSymbolAddress((void**)&wvl, g_wvt_l);
    cudaGetSymbolAddress((void**)&woh, g_wot_h);
    cudaGetSymbolAddress((void**)&wol, g_wot_l);

    const int M = Bsz * Tt;   // 4096
    const int n4 = M * Dd / 4;

    cudaFuncSetAttribute(mma_gemm, cudaFuncAttributeMaxDynamicSharedMemorySize, GEMM_SMEM);

    // conversions
    split_kernel<<<4096, 256>>>(x, xsh, xsl, n4);
    tsplit_kernel<<<dim3(Dd/32, Dd/32), dim3(32,8)>>>(Wq, wqh, wql, Dd, Dd);
    tsplit_kernel<<<dim3((KVh*HD)/32, Dd/32), dim3(32,8)>>>(Wk, wkh, wkl, Dd, KVh*HD);
    tsplit_kernel<<<dim3((KVh*HD)/32, Dd/32), dim3(32,8)>>>(Wv, wvh, wvl, Dd, KVh*HD);
    tsplit_kernel<<<dim3(Dd/32, Dd/32), dim3(32,8)>>>(Wo, woh, wol, Dd, Dd);

    // projections (mma.sync bf16x3)
    mma_gemm<<<dim3(Dd/128, M/128), 256, GEMM_SMEM>>>(xsh, xsl, wqh, wql, q, M, Dd, Dd);
    mma_gemm<<<dim3((KVh*HD)/128, M/128), 256, GEMM_SMEM>>>(xsh, xsl, wkh, wkl, k, M, KVh*HD, Dd);
    mma_gemm<<<dim3((KVh*HD)/128, M/128), 256, GEMM_SMEM>>>(xsh, xsl, wvh, wvl, v, M, KVh*HD, Dd);

    // RoPE
    rope_kernel<<<(Bsz * Tt * Hh) / 2, 128>>>(q, Hh);
    rope_kernel<<<(Bsz * Tt * KVh) / 2, 128>>>(k, KVh);

    // flash attention (fp32)
    int smem = (3 * FBQ * HD + FBQ * SSTR + 3 * FBQ) * (int)sizeof(float);
    cudaFuncSetAttribute(flash_kernel, cudaFuncAttributeMaxDynamicSharedMemorySize, smem);
    flash_kernel<<<dim3(Tt / FBQ, Hh, Bsz), 256, smem>>>(q, k, v, o);

    // output projection
    split_kernel<<<4096, 256>>>(o, osh, osl, n4);
    mma_gemm<<<dim3(Dd/128, M/128), 256, GEMM_SMEM>>>(osh, osl, woh, wol, out, M, Dd, Dd);
}

// round 4
// speedup vs baseline: 4.3334x; 3.0799x over previous
#include <cuda_runtime.h>
#include <cuda_bf16.h>
#include <cstdint>
#include <math.h>

#define Bsz 2
#define Tt 2048
#define Dd 2048
#define Hh 16
#define KVh 4
#define HD 128
#define GQ (Hh/KVh)

// ---------------- scratch (__device__ globals; no allocation allowed) ----------------
__device__ float g_q[(size_t)Bsz*Tt*Dd];
__device__ float g_k[(size_t)Bsz*Tt*KVh*HD];
__device__ float g_v[(size_t)Bsz*Tt*KVh*HD];
__device__ float g_o[(size_t)Bsz*Tt*Dd];

__device__ __nv_bfloat16 g_xs_h[(size_t)Bsz*Tt*Dd];
__device__ __nv_bfloat16 g_xs_l[(size_t)Bsz*Tt*Dd];
__device__ __nv_bfloat16 g_os_h[(size_t)Bsz*Tt*Dd];
__device__ __nv_bfloat16 g_os_l[(size_t)Bsz*Tt*Dd];
__device__ __nv_bfloat16 g_wqt_h[(size_t)Dd*Dd];
__device__ __nv_bfloat16 g_wqt_l[(size_t)Dd*Dd];
__device__ __nv_bfloat16 g_wkt_h[(size_t)KVh*HD*Dd];
__device__ __nv_bfloat16 g_wkt_l[(size_t)KVh*HD*Dd];
__device__ __nv_bfloat16 g_wvt_h[(size_t)KVh*HD*Dd];
__device__ __nv_bfloat16 g_wvt_l[(size_t)KVh*HD*Dd];
__device__ __nv_bfloat16 g_wot_h[(size_t)Dd*Dd];
__device__ __nv_bfloat16 g_wot_l[(size_t)Dd*Dd];

// flash inputs: permuted [B*heads, T, HD] split bf16
__device__ __nv_bfloat16 g_qh[(size_t)Bsz*Hh*Tt*HD];
__device__ __nv_bfloat16 g_ql[(size_t)Bsz*Hh*Tt*HD];
__device__ __nv_bfloat16 g_kh[(size_t)Bsz*KVh*Tt*HD];
__device__ __nv_bfloat16 g_kl[(size_t)Bsz*KVh*Tt*HD];
__device__ __nv_bfloat16 g_vh[(size_t)Bsz*KVh*Tt*HD];
__device__ __nv_bfloat16 g_vl[(size_t)Bsz*KVh*Tt*HD];

// ---------------- helpers ----------------
__device__ __forceinline__ uint32_t smem_u32(const void* p) {
    uint32_t a;
    asm("{ .reg .u64 t; cvta.to.shared.u64 t, %1; cvt.u32.u64 %0, t; }" : "=r"(a) : "l"(p));
    return a;
}

#define CP_ASYNC16(dst, src) \
    asm volatile("cp.async.cg.shared.global [%0], [%1], 16;" :: "r"(dst), "l"(src))
#define CP_COMMIT() asm volatile("cp.async.commit_group;")
#define CP_WAIT1()  asm volatile("cp.async.wait_group 1;")
#define CP_WAIT0()  asm volatile("cp.async.wait_group 0;")

#define LDSM_X4(r0, r1, r2, r3, addr) \
    asm volatile("ldmatrix.sync.aligned.m8n8.x4.shared.b16 {%0,%1,%2,%3}, [%4];" \
        : "=r"(r0), "=r"(r1), "=r"(r2), "=r"(r3) : "r"(addr))

#define LDSM_X4T(r0, r1, r2, r3, addr) \
    asm volatile("ldmatrix.sync.aligned.m8n8.x4.trans.shared.b16 {%0,%1,%2,%3}, [%4];" \
        : "=r"(r0), "=r"(r1), "=r"(r2), "=r"(r3) : "r"(addr))

#define MMA16816(c, a, b0, b1) \
    asm volatile("mma.sync.aligned.m16n8k16.row.col.f32.bf16.bf16.f32 " \
        "{%0,%1,%2,%3},{%4,%5,%6,%7},{%8,%9},{%0,%1,%2,%3};" \
        : "+f"((c)[0]), "+f"((c)[1]), "+f"((c)[2]), "+f"((c)[3]) \
        : "r"((a)[0]), "r"((a)[1]), "r"((a)[2]), "r"((a)[3]), "r"(b0), "r"(b1))

__device__ __forceinline__ uint32_t packbf2(__nv_bfloat16 lo, __nv_bfloat16 hi) {
    union { __nv_bfloat162 v; uint32_t u; } cv;
    cv.v.x = lo; cv.v.y = hi;
    return cv.u;
}

// ---------------- conversion kernels ----------------
__global__ void split_kernel(const float* __restrict__ A,
                             __nv_bfloat16* __restrict__ H,
                             __nv_bfloat16* __restrict__ L, int n4)
{
    int i = blockIdx.x * blockDim.x + threadIdx.x;
    int stride = gridDim.x * blockDim.x;
    for (; i < n4; i += stride) {
        float4 a = ((const float4*)A)[i];
        __nv_bfloat16 h0 = __float2bfloat16(a.x);
        __nv_bfloat16 h1 = __float2bfloat16(a.y);
        __nv_bfloat16 h2 = __float2bfloat16(a.z);
        __nv_bfloat16 h3 = __float2bfloat16(a.w);
        __nv_bfloat16 l0 = __float2bfloat16(a.x - __bfloat162float(h0));
        __nv_bfloat16 l1 = __float2bfloat16(a.y - __bfloat162float(h1));
        __nv_bfloat16 l2 = __float2bfloat16(a.z - __bfloat162float(h2));
        __nv_bfloat16 l3 = __float2bfloat16(a.w - __bfloat162float(h3));
        ((__nv_bfloat162*)H)[2*i]   = __nv_bfloat162(h0, h1);
        ((__nv_bfloat162*)H)[2*i+1] = __nv_bfloat162(h2, h3);
        ((__nv_bfloat162*)L)[2*i]   = __nv_bfloat162(l0, l1);
        ((__nv_bfloat162*)L)[2*i+1] = __nv_bfloat162(l2, l3);
    }
}

// src [B, T, nh, HD] fp32  ->  dst [B*nh, T, HD] split bf16 (optionally scaled)
__global__ void split_perm_kernel(const float* __restrict__ src,
                                  __nv_bfloat16* __restrict__ H,
                                  __nv_bfloat16* __restrict__ L,
                                  int nh, float scale)
{
    size_t idx = (size_t)blockIdx.x * blockDim.x + threadIdx.x;
    int d = idx & (HD - 1);
    size_t r = idx >> 7;
    int hh = r % nh;
    size_t bt = r / nh;
    int t = bt % Tt;
    int b = bt / Tt;
    float v = src[idx] * scale;
    __nv_bfloat16 hi = __float2bfloat16(v);
    size_t o = ((size_t)(b * nh + hh) * Tt + t) * HD + d;
    H[o] = hi;
    L[o] = __float2bfloat16(v - __bfloat162float(hi));
}

// W[K,N] fp32 -> Wt_hi/lo[N,K] bf16 (transpose + split)
__global__ void tsplit_kernel(const float* __restrict__ W,
                              __nv_bfloat16* __restrict__ Th,
                              __nv_bfloat16* __restrict__ Tl, int K, int N)
{
    __shared__ float t[32][33];
    int n0 = blockIdx.x * 32, k0 = blockIdx.y * 32;
    int tx = threadIdx.x, ty0 = threadIdx.y;
#pragma unroll
    for (int j = 0; j < 4; j++) {
        int ty = ty0 + j * 8;
        t[ty][tx] = W[(size_t)(k0 + ty) * N + n0 + tx];
    }
    __syncthreads();
#pragma unroll
    for (int j = 0; j < 4; j++) {
        int ty = ty0 + j * 8;
        float v = t[tx][ty];
        size_t o = (size_t)(n0 + ty) * K + k0 + tx;
        __nv_bfloat16 h = __float2bfloat16(v);
        Th[o] = h;
        Tl[o] = __float2bfloat16(v - __bfloat162float(h));
    }
}

// ---------------- mma.sync bf16x3 GEMM (unchanged from R3) ----------------
#define KSP 40
#define TILE_B (128 * KSP * 2)
#define STAGE_B (4 * TILE_B)
#define NSTG 3
#define GEMM_SMEM (NSTG * STAGE_B)

__global__ void __launch_bounds__(256, 1) mma_gemm(
    const __nv_bfloat16* __restrict__ Ah, const __nv_bfloat16* __restrict__ Al,
    const __nv_bfloat16* __restrict__ Bh, const __nv_bfloat16* __restrict__ Bl,
    float* __restrict__ C, int M, int N, int K)
{
    extern __shared__ char sm[];
    uint32_t smem_base = smem_u32(sm);
    int tid = threadIdx.x;
    int wid = tid >> 5, lane = tid & 31;
    int wm = wid >> 2, wn = wid & 3;

    int m0 = blockIdx.y * 128, n0 = blockIdx.x * 128;
    int nstage = K / 32;

    float acc[4][4][4];
#pragma unroll
    for (int a = 0; a < 4; a++)
#pragma unroll
        for (int b = 0; b < 4; b++)
#pragma unroll
            for (int c = 0; c < 4; c++) acc[a][b][c] = 0.f;

    auto load_stage = [&](int kc, int s) {
        int kcol = kc * 32;
        uint32_t sb = smem_base + s * STAGE_B;
#pragma unroll
        for (int i = 0; i < 8; i++) {
            int c = tid + i * 256;
            int tile = c >> 9;
            int cid = c & 511;
            int row = cid >> 2;
            int kch = cid & 3;
            const __nv_bfloat16* src;
            if (tile == 0)      src = Ah + (size_t)(m0 + row) * K + kcol + kch * 8;
            else if (tile == 1) src = Al + (size_t)(m0 + row) * K + kcol + kch * 8;
            else if (tile == 2) src = Bh + (size_t)(n0 + row) * K + kcol + kch * 8;
            else                src = Bl + (size_t)(n0 + row) * K + kcol + kch * 8;
            uint32_t dst = sb + tile * TILE_B + (row * KSP + kch * 8) * 2;
            CP_ASYNC16(dst, src);
        }
    };

    load_stage(0, 0); CP_COMMIT();
    load_stage(1, 1); CP_COMMIT();

    uint32_t aoff = ((wm * 64 + (lane & 15)) * KSP + ((lane >> 4) << 3)) * 2;
    uint32_t boff = ((wn * 32 + ((lane >> 4) << 3) + (lane & 7)) * KSP + (((lane >> 3) & 1) << 3)) * 2;

    for (int kc = 0; kc < nstage; kc++) {
        CP_WAIT1();
        __syncthreads();
        if (kc + 2 < nstage) load_stage(kc + 2, (kc + 2) % NSTG);
        CP_COMMIT();

        uint32_t sb = smem_base + (kc % NSTG) * STAGE_B;
        uint32_t aHi = sb + aoff;
        uint32_t aLo = aHi + TILE_B;
        uint32_t bHi = sb + 2 * TILE_B + boff;
        uint32_t bLo = bHi + TILE_B;

#pragma unroll
        for (int kk = 0; kk < 2; kk++) {
            uint32_t ko = kk * 32;
            uint32_t ah[4][4], al[4][4], bh[2][4], bl[2][4];
#pragma unroll
            for (int mt = 0; mt < 4; mt++) {
                LDSM_X4(ah[mt][0], ah[mt][1], ah[mt][2], ah[mt][3], aHi + mt * 16 * KSP * 2 + ko);
                LDSM_X4(al[mt][0], al[mt][1], al[mt][2], al[mt][3], aLo + mt * 16 * KSP * 2 + ko);
            }
#pragma unroll
            for (int pr = 0; pr < 2; pr++) {
                LDSM_X4(bh[pr][0], bh[pr][1], bh[pr][2], bh[pr][3], bHi + pr * 16 * KSP * 2 + ko);
                LDSM_X4(bl[pr][0], bl[pr][1], bl[pr][2], bl[pr][3], bLo + pr * 16 * KSP * 2 + ko);
            }
#pragma unroll
            for (int mt = 0; mt < 4; mt++)
#pragma unroll
                for (int nt = 0; nt < 4; nt++) {
                    int pr = nt >> 1, ix = (nt & 1) * 2;
                    MMA16816(acc[mt][nt], ah[mt], bh[pr][ix], bh[pr][ix + 1]);
                    MMA16816(acc[mt][nt], ah[mt], bl[pr][ix], bl[pr][ix + 1]);
                    MMA16816(acc[mt][nt], al[mt], bh[pr][ix], bh[pr][ix + 1]);
                }
        }
    }

#pragma unroll
    for (int mt = 0; mt < 4; mt++)
#pragma unroll
        for (int nt = 0; nt < 4; nt++) {
            int row = m0 + wm * 64 + mt * 16 + (lane >> 2);
            int col = n0 + wn * 32 + nt * 8 + (lane & 3) * 2;
            *(float2*)&C[(size_t)row * N + col]       = make_float2(acc[mt][nt][0], acc[mt][nt][1]);
            *(float2*)&C[(size_t)(row + 8) * N + col] = make_float2(acc[mt][nt][2], acc[mt][nt][3]);
        }
}

// ---------------- RoPE ----------------
__global__ void rope_kernel(float* __restrict__ buf, int nh)
{
    int row = blockIdx.x * 2 + (threadIdx.x >> 6);
    int f = threadIdx.x & 63;
    float* r = buf + (size_t)row * HD;
    float x1 = r[2 * f];
    float x2 = r[2 * f + 1];
    int t = (row / nh) % Tt;
    float inv = 1.0f / powf(10000.0f, (float)f * (1.0f / 64.0f));
    float ang = (float)t * inv;
    float s, c;
    sincosf(ang, &s, &c);
    __syncthreads();
    r[f]      = x1 * c - x2 * s;
    r[64 + f] = x1 * s + x2 * c;
}

// ---------------- Flash attention: mma.sync split-bf16 ----------------
// CTA: 64 q-rows, 4 warps (16 rows each). K/V tiles of 64 rows. HD=128.
#define FSTR 136                    // halves per smem row (272B, conflict-free for ldsm)
#define FTB  (64 * FSTR * 2)        // 17408 bytes per tile
#define FLASH_SMEM (6 * FTB)        // Qh Ql Kh Kl Vh Vl = 104448

__global__ void __launch_bounds__(128) flash_mma(
    const __nv_bfloat16* __restrict__ Qh, const __nv_bfloat16* __restrict__ Ql,
    const __nv_bfloat16* __restrict__ Kh, const __nv_bfloat16* __restrict__ Kl,
    const __nv_bfloat16* __restrict__ Vh, const __nv_bfloat16* __restrict__ Vl,
    float* __restrict__ O)
{
    extern __shared__ char sm[];
    uint32_t sb = smem_u32(sm);
    int tid = threadIdx.x, lane = tid & 31, wm = tid >> 5;
    int qt = blockIdx.x;
    int h = blockIdx.y, b = blockIdx.z;
    int q0 = qt * 64;
    int kvh = h / GQ;

    const __nv_bfloat16* Qhp = Qh + ((size_t)(b * Hh + h) * Tt + q0) * HD;
    const __nv_bfloat16* Qlp = Ql + ((size_t)(b * Hh + h) * Tt + q0) * HD;
    const __nv_bfloat16* Khp = Kh + (size_t)(b * KVh + kvh) * Tt * HD;
    const __nv_bfloat16* Klp = Kl + (size_t)(b * KVh + kvh) * Tt * HD;
    const __nv_bfloat16* Vhp = Vh + (size_t)(b * KVh + kvh) * Tt * HD;
    const __nv_bfloat16* Vlp = Vl + (size_t)(b * KVh + kvh) * Tt * HD;

    // Q tiles -> smem (cp.async)
#pragma unroll
    for (int i = 0; i < 8; i++) {
        int ch = tid + i * 128;
        int r = ch >> 4, c = ch & 15;
        uint32_t off = (uint32_t)(r * FSTR + c * 8) * 2;
        CP_ASYNC16(sb + off,       Qhp + (size_t)r * HD + c * 8);
        CP_ASYNC16(sb + FTB + off, Qlp + (size_t)r * HD + c * 8);
    }
    CP_COMMIT();

    float oc[16][4];
#pragma unroll
    for (int i = 0; i < 16; i++)
#pragma unroll
        for (int e = 0; e < 4; e++) oc[i][e] = 0.f;
    float mrow[2] = { -1e30f, -1e30f };
    float lrow[2] = { 0.f, 0.f };

    // ldsm base offsets
    uint32_t q_add = (uint32_t)((wm * 16 + (lane & 15)) * FSTR + ((lane >> 4) << 3)) * 2;
    uint32_t k_add = (uint32_t)(((lane >> 4) * 8 + (lane & 7)) * FSTR + (((lane >> 3) & 1) << 3)) * 2;
    // V ldsm.trans: lanes in 4 groups of 8
    int vg = lane >> 3, vl8 = lane & 7;
    uint32_t v_add = (uint32_t)(((vg & 1) * 8 + vl8) * FSTR + ((vg >> 1) << 3)) * 2;

    int ntile = qt + 1;
    for (int j = 0; j < ntile; j++) {
        // K/V tile j -> smem
        const __nv_bfloat16* kh = Khp + (size_t)j * 64 * HD;
        const __nv_bfloat16* kl = Klp + (size_t)j * 64 * HD;
        const __nv_bfloat16* vh = Vhp + (size_t)j * 64 * HD;
        const __nv_bfloat16* vl = Vlp + (size_t)j * 64 * HD;
#pragma unroll
        for (int i = 0; i < 8; i++) {
            int ch = tid + i * 128;
            int r = ch >> 4, c = ch & 15;
            uint32_t off = (uint32_t)(r * FSTR + c * 8) * 2;
            size_t go = (size_t)r * HD + c * 8;
            CP_ASYNC16(sb + 2 * FTB + off, kh + go);
            CP_ASYNC16(sb + 3 * FTB + off, kl + go);
            CP_ASYNC16(sb + 4 * FTB + off, vh + go);
            CP_ASYNC16(sb + 5 * FTB + off, vl + go);
        }
        CP_COMMIT();
        CP_WAIT0();
        __syncthreads();

        // ---- S = Q @ K^T (split: qh*kh + qh*kl + ql*kh) ----
        float sc[8][4];
#pragma unroll
        for (int nt = 0; nt < 8; nt++)
#pragma unroll
            for (int e = 0; e < 4; e++) sc[nt][e] = 0.f;

#pragma unroll
        for (int kb = 0; kb < 8; kb++) {
            uint32_t qh4[4], ql4[4];
            uint32_t ko = kb * 32;   // 16 halves
            LDSM_X4(qh4[0], qh4[1], qh4[2], qh4[3], sb + q_add + ko);
            LDSM_X4(ql4[0], ql4[1], ql4[2], ql4[3], sb + FTB + q_add + ko);
            uint32_t kh4[4][4], kl4[4][4];
#pragma unroll
            for (int pr = 0; pr < 4; pr++) {
                uint32_t ra = pr * 16 * FSTR * 2 + ko;
                LDSM_X4(kh4[pr][0], kh4[pr][1], kh4[pr][2], kh4[pr][3], sb + 2 * FTB + k_add + ra);
                LDSM_X4(kl4[pr][0], kl4[pr][1], kl4[pr][2], kl4[pr][3], sb + 3 * FTB + k_add + ra);
            }
#pragma unroll
            for (int nt = 0; nt < 8; nt++) {
                int pr = nt >> 1, ix = (nt & 1) * 2;
                MMA16816(sc[nt], qh4, kh4[pr][ix], kh4[pr][ix + 1]);
                MMA16816(sc[nt], qh4, kl4[pr][ix], kl4[pr][ix + 1]);
                MMA16816(sc[nt], ql4, kh4[pr][ix], kh4[pr][ix + 1]);
            }
        }

        // ---- causal mask (diagonal tile only) ----
        if (j == ntile - 1) {
            int row0 = q0 + wm * 16 + (lane >> 2);
#pragma unroll
            for (int nt = 0; nt < 8; nt++) {
                int col = j * 64 + nt * 8 + (lane & 3) * 2;
#pragma unroll
                for (int e = 0; e < 4; e++) {
                    int cc = col + (e & 1);
                    int rr = row0 + ((e >> 1) << 3);
                    if (cc > rr) sc[nt][e] = -1e30f;
                }
            }
        }

        // ---- online softmax on fragments ----
#pragma unroll
        for (int half = 0; half < 2; half++) {
            int e0 = half * 2;
            float mx = -1e30f;
#pragma unroll
            for (int nt = 0; nt < 8; nt++)
                mx = fmaxf(mx, fmaxf(sc[nt][e0], sc[nt][e0 + 1]));
            mx = fmaxf(mx, __shfl_xor_sync(0xffffffff, mx, 1));
            mx = fmaxf(mx, __shfl_xor_sync(0xffffffff, mx, 2));
            float mnew = fmaxf(mrow[half], mx);
            float alpha = __expf(mrow[half] - mnew);
            float sum = 0.f;
#pragma unroll
            for (int nt = 0; nt < 8; nt++) {
                float p0 = __expf(sc[nt][e0]     - mnew);
                float p1 = __expf(sc[nt][e0 + 1] - mnew);
                sc[nt][e0] = p0; sc[nt][e0 + 1] = p1;
                sum += p0 + p1;
            }
            sum += __shfl_xor_sync(0xffffffff, sum, 1);
            sum += __shfl_xor_sync(0xffffffff, sum, 2);
            lrow[half] = lrow[half] * alpha + sum;
            mrow[half] = mnew;
#pragma unroll
            for (int nt = 0; nt < 16; nt++) {
                oc[nt][e0]     *= alpha;
                oc[nt][e0 + 1] *= alpha;
            }
        }

        // ---- O += P @ V (split: ph*vh + ph*vl + pl*vh) ----
#pragma unroll
        for (int kb2 = 0; kb2 < 4; kb2++) {
            int nt0 = kb2 * 2, nt1 = nt0 + 1;
            uint32_t ph[4], pl[4];
#pragma unroll
            for (int r4 = 0; r4 < 4; r4++) {
                int nts = (r4 >> 1) ? nt1 : nt0;
                int eb = (r4 & 1) * 2;
                float x0 = sc[nts][eb], x1 = sc[nts][eb + 1];
                __nv_bfloat16 h0 = __float2bfloat16(x0);
                __nv_bfloat16 h1 = __float2bfloat16(x1);
                ph[r4] = packbf2(h0, h1);
                pl[r4] = packbf2(__float2bfloat16(x0 - __bfloat162float(h0)),
                                 __float2bfloat16(x1 - __bfloat162float(h1)));
            }
            // a-frag order: a0=(r,k0-7), a1=(r+8,k0-7), a2=(r,k8-15), a3=(r+8,k8-15)
            uint32_t pha[4] = { ph[0], ph[1], ph[2], ph[3] };
            uint32_t pla[4] = { pl[0], pl[1], pl[2], pl[3] };

            uint32_t vrow = kb2 * 16 * FSTR * 2;
#pragma unroll
            for (int np = 0; np < 8; np++) {
                uint32_t va = sb + 4 * FTB + v_add + vrow + np * 32;  // np*16 halves
                uint32_t vb = va + FTB;
                uint32_t v4h[4], v4l[4];
                LDSM_X4T(v4h[0], v4h[1], v4h[2], v4h[3], va);
                LDSM_X4T(v4l[0], v4l[1], v4l[2], v4l[3], vb);
                int nt = np * 2;
                MMA16816(oc[nt], pha, v4h[0], v4h[1]);
                MMA16816(oc[nt], pha, v4l[0], v4l[1]);
                MMA16816(oc[nt], pla, v4h[0], v4h[1]);
                MMA16816(oc[nt + 1], pha, v4h[2], v4h[3]);
                MMA16816(oc[nt + 1], pha, v4l[2], v4l[3]);
                MMA16816(oc[nt + 1], pla, v4h[2], v4h[3]);
            }
        }
        __syncthreads();   // done reading K/V before next overwrite
    }

    // ---- epilogue: normalize, write O in [B,T,H,HD] ----
#pragma unroll
    for (int half = 0; half < 2; half++) {
        float inv_l = 1.0f / lrow[half];
        int row = q0 + wm * 16 + (lane >> 2) + half * 8;
        float* Op = O + (((size_t)b * Tt + row) * Hh + h) * HD;
#pragma unroll
        for (int nt = 0; nt < 16; nt++) {
            int d = nt * 8 + (lane & 3) * 2;
            *(float2*)(Op + d) = make_float2(oc[nt][half * 2] * inv_l,
                                             oc[nt][half * 2 + 1] * inv_l);
        }
    }
}

// ---------------- launch ----------------
extern "C" void kernel_launch(void* const* d_in, const int* in_sizes, int n_in,
                              void* d_out, int out_size)
{
    const float* x  = (const float*)d_in[0];
    const float* Wq = (const float*)d_in[1];
    const float* Wk = (const float*)d_in[2];
    const float* Wv = (const float*)d_in[3];
    const float* Wo = (const float*)d_in[4];
    float* out = (float*)d_out;

    float *q, *k, *v, *o;
    cudaGetSymbolAddress((void**)&q, g_q);
    cudaGetSymbolAddress((void**)&k, g_k);
    cudaGetSymbolAddress((void**)&v, g_v);
    cudaGetSymbolAddress((void**)&o, g_o);
    __nv_bfloat16 *xsh, *xsl, *osh, *osl;
    __nv_bfloat16 *wqh, *wql, *wkh, *wkl, *wvh, *wvl, *woh, *wol;
    __nv_bfloat16 *qh, *ql, *kh, *kl, *vh, *vl;
    cudaGetSymbolAddress((void**)&xsh, g_xs_h);
    cudaGetSymbolAddress((void**)&xsl, g_xs_l);
    cudaGetSymbolAddress((void**)&osh, g_os_h);
    cudaGetSymbolAddress((void**)&osl, g_os_l);
    cudaGetSymbolAddress((void**)&wqh, g_wqt_h);
    cudaGetSymbolAddress((void**)&wql, g_wqt_l);
    cudaGetSymbolAddress((void**)&wkh, g_wkt_h);
    cudaGetSymbolAddress((void**)&wkl, g_wkt_l);
    cudaGetSymbolAddress((void**)&wvh, g_wvt_h);
    cudaGetSymbolAddress((void**)&wvl, g_wvt_l);
    cudaGetSymbolAddress((void**)&woh, g_wot_h);
    cudaGetSymbolAddress((void**)&wol, g_wot_l);
    cudaGetSymbolAddress((void**)&qh, g_qh);
    cudaGetSymbolAddress((void**)&ql, g_ql);
    cudaGetSymbolAddress((void**)&kh, g_kh);
    cudaGetSymbolAddress((void**)&kl, g_kl);
    cudaGetSymbolAddress((void**)&vh, g_vh);
    cudaGetSymbolAddress((void**)&vl, g_vl);

    const int M = Bsz * Tt;   // 4096
    const int n4 = M * Dd / 4;

    cudaFuncSetAttribute(mma_gemm, cudaFuncAttributeMaxDynamicSharedMemorySize, GEMM_SMEM);
    cudaFuncSetAttribute(flash_mma, cudaFuncAttributeMaxDynamicSharedMemorySize, FLASH_SMEM);

    // conversions
    split_kernel<<<4096, 256>>>(x, xsh, xsl, n4);
    tsplit_kernel<<<dim3(Dd/32, Dd/32), dim3(32,8)>>>(Wq, wqh, wql, Dd, Dd);
    tsplit_kernel<<<dim3((KVh*HD)/32, Dd/32), dim3(32,8)>>>(Wk, wkh, wkl, Dd, KVh*HD);
    tsplit_kernel<<<dim3((KVh*HD)/32, Dd/32), dim3(32,8)>>>(Wv, wvh, wvl, Dd, KVh*HD);
    tsplit_kernel<<<dim3(Dd/32, Dd/32), dim3(32,8)>>>(Wo, woh, wol, Dd, Dd);

    // projections (mma.sync bf16x3)
    mma_gemm<<<dim3(Dd/128, M/128), 256, GEMM_SMEM>>>(xsh, xsl, wqh, wql, q, M, Dd, Dd);
    mma_gemm<<<dim3((KVh*HD)/128, M/128), 256, GEMM_SMEM>>>(xsh, xsl, wkh, wkl, k, M, KVh*HD, Dd);
    mma_gemm<<<dim3((KVh*HD)/128, M/128), 256, GEMM_SMEM>>>(xsh, xsl, wvh, wvl, v, M, KVh*HD, Dd);

    // RoPE (fp32, in place)
    rope_kernel<<<(Bsz * Tt * Hh) / 2, 128>>>(q, Hh);
    rope_kernel<<<(Bsz * Tt * KVh) / 2, 128>>>(k, KVh);

    // permute + split to bf16 (Q pre-scaled by 1/sqrt(HD))
    const float scale = 0.08838834764831845f;
    split_perm_kernel<<<(Bsz*Tt*Hh*HD)/256, 256>>>(q, qh, ql, Hh, scale);
    split_perm_kernel<<<(Bsz*Tt*KVh*HD)/256, 256>>>(k, kh, kl, KVh, 1.0f);
    split_perm_kernel<<<(Bsz*Tt*KVh*HD)/256, 256>>>(v, vh, vl, KVh, 1.0f);

    // flash attention (tensor cores)
    flash_mma<<<dim3(Tt/64, Hh, Bsz), 128, FLASH_SMEM>>>(qh, ql, kh, kl, vh, vl, o);

    // output projection
    split_kernel<<<4096, 256>>>(o, osh, osl, n4);
    mma_gemm<<<dim3(Dd/128, M/128), 256, GEMM_SMEM>>>(osh, osl, woh, wol, out, M, Dd, Dd);
}

// round 5
// speedup vs baseline: 4.9826x; 1.1498x over previous
#include <cuda_runtime.h>
#include <cuda_bf16.h>
#include <cstdint>
#include <math.h>

#define Bsz 2
#define Tt 2048
#define Dd 2048
#define Hh 16
#define KVh 4
#define HD 128
#define GQ (Hh/KVh)
#define NQKV 3072

// ---------------- scratch ----------------
__device__ float g_qkv[(size_t)Bsz*Tt*NQKV];          // fused QKV output [4096, 3072]

__device__ __nv_bfloat16 g_xs_h[(size_t)Bsz*Tt*Dd];
__device__ __nv_bfloat16 g_xs_l[(size_t)Bsz*Tt*Dd];
__device__ __nv_bfloat16 g_os_h[(size_t)Bsz*Tt*Dd];
__device__ __nv_bfloat16 g_os_l[(size_t)Bsz*Tt*Dd];
__device__ __nv_bfloat16 g_wqkvt_h[(size_t)NQKV*Dd];
__device__ __nv_bfloat16 g_wqkvt_l[(size_t)NQKV*Dd];
__device__ __nv_bfloat16 g_wot_h[(size_t)Dd*Dd];
__device__ __nv_bfloat16 g_wot_l[(size_t)Dd*Dd];

__device__ __nv_bfloat16 g_qh[(size_t)Bsz*Hh*Tt*HD];
__device__ __nv_bfloat16 g_ql[(size_t)Bsz*Hh*Tt*HD];
__device__ __nv_bfloat16 g_kh[(size_t)Bsz*KVh*Tt*HD];
__device__ __nv_bfloat16 g_kl[(size_t)Bsz*KVh*Tt*HD];
__device__ __nv_bfloat16 g_vh[(size_t)Bsz*KVh*Tt*HD];
__device__ __nv_bfloat16 g_vl[(size_t)Bsz*KVh*Tt*HD];

// ---------------- helpers ----------------
__device__ __forceinline__ uint32_t smem_u32(const void* p) {
    uint32_t a;
    asm("{ .reg .u64 t; cvta.to.shared.u64 t, %1; cvt.u32.u64 %0, t; }" : "=r"(a) : "l"(p));
    return a;
}

#define CP_ASYNC16(dst, src) \
    asm volatile("cp.async.cg.shared.global [%0], [%1], 16;" :: "r"(dst), "l"(src))
#define CP_COMMIT() asm volatile("cp.async.commit_group;")
#define CP_WAIT0()  asm volatile("cp.async.wait_group 0;")

#define LDSM_X4(r0, r1, r2, r3, addr) \
    asm volatile("ldmatrix.sync.aligned.m8n8.x4.shared.b16 {%0,%1,%2,%3}, [%4];" \
        : "=r"(r0), "=r"(r1), "=r"(r2), "=r"(r3) : "r"(addr))

#define LDSM_X4T(r0, r1, r2, r3, addr) \
    asm volatile("ldmatrix.sync.aligned.m8n8.x4.trans.shared.b16 {%0,%1,%2,%3}, [%4];" \
        : "=r"(r0), "=r"(r1), "=r"(r2), "=r"(r3) : "r"(addr))

#define MMA16816(c, a, b0, b1) \
    asm volatile("mma.sync.aligned.m16n8k16.row.col.f32.bf16.bf16.f32 " \
        "{%0,%1,%2,%3},{%4,%5,%6,%7},{%8,%9},{%0,%1,%2,%3};" \
        : "+f"((c)[0]), "+f"((c)[1]), "+f"((c)[2]), "+f"((c)[3]) \
        : "r"((a)[0]), "r"((a)[1]), "r"((a)[2]), "r"((a)[3]), "r"(b0), "r"(b1))

__device__ __forceinline__ uint32_t packbf2(__nv_bfloat16 lo, __nv_bfloat16 hi) {
    union { __nv_bfloat162 v; uint32_t u; } cv;
    cv.v.x = lo; cv.v.y = hi;
    return cv.u;
}

// ---------------- conversion kernels ----------------
__global__ void split_kernel(const float* __restrict__ A,
                             __nv_bfloat16* __restrict__ H,
                             __nv_bfloat16* __restrict__ L, int n4)
{
    int i = blockIdx.x * blockDim.x + threadIdx.x;
    int stride = gridDim.x * blockDim.x;
    for (; i < n4; i += stride) {
        float4 a = ((const float4*)A)[i];
        __nv_bfloat16 h0 = __float2bfloat16(a.x);
        __nv_bfloat16 h1 = __float2bfloat16(a.y);
        __nv_bfloat16 h2 = __float2bfloat16(a.z);
        __nv_bfloat16 h3 = __float2bfloat16(a.w);
        __nv_bfloat16 l0 = __float2bfloat16(a.x - __bfloat162float(h0));
        __nv_bfloat16 l1 = __float2bfloat16(a.y - __bfloat162float(h1));
        __nv_bfloat16 l2 = __float2bfloat16(a.z - __bfloat162float(h2));
        __nv_bfloat16 l3 = __float2bfloat16(a.w - __bfloat162float(h3));
        ((__nv_bfloat162*)H)[2*i]   = __nv_bfloat162(h0, h1);
        ((__nv_bfloat162*)H)[2*i+1] = __nv_bfloat162(h2, h3);
        ((__nv_bfloat162*)L)[2*i]   = __nv_bfloat162(l0, l1);
        ((__nv_bfloat162*)L)[2*i+1] = __nv_bfloat162(l2, l3);
    }
}

// W[K,N] fp32 -> Wt_hi/lo[N,K] bf16 (transpose + split)
__global__ void tsplit_kernel(const float* __restrict__ W,
                              __nv_bfloat16* __restrict__ Th,
                              __nv_bfloat16* __restrict__ Tl, int K, int N)
{
    __shared__ float t[32][33];
    int n0 = blockIdx.x * 32, k0 = blockIdx.y * 32;
    int tx = threadIdx.x, ty0 = threadIdx.y;
#pragma unroll
    for (int j = 0; j < 4; j++) {
        int ty = ty0 + j * 8;
        t[ty][tx] = W[(size_t)(k0 + ty) * N + n0 + tx];
    }
    __syncthreads();
#pragma unroll
    for (int j = 0; j < 4; j++) {
        int ty = ty0 + j * 8;
        float v = t[tx][ty];
        size_t o = (size_t)(n0 + ty) * K + k0 + tx;
        __nv_bfloat16 h = __float2bfloat16(v);
        Th[o] = h;
        Tl[o] = __float2bfloat16(v - __bfloat162float(h));
    }
}

// RoPE + split + permute: src fp32 [B*T, srcstride] (cols colbase + h*HD)
//   -> H/L bf16 [B*nh, T, HD], value scaled by `scale`
__global__ void rope_split_kernel(const float* __restrict__ src,
                                  __nv_bfloat16* __restrict__ H,
                                  __nv_bfloat16* __restrict__ L,
                                  int nh, int colbase, int sstride, float scale)
{
    int row = blockIdx.x * 2 + (threadIdx.x >> 6);
    int f = threadIdx.x & 63;
    int hh = row % nh;
    int bt = row / nh;
    int t = bt % Tt;
    int b = bt / Tt;
    const float* r = src + (size_t)bt * sstride + colbase + hh * HD;
    float x1 = r[2 * f];
    float x2 = r[2 * f + 1];
    float inv = powf(10000.0f, -(float)f * (1.0f / 64.0f));
    float ang = (float)t * inv;
    float s, c;
    sincosf(ang, &s, &c);
    float v1 = (x1 * c - x2 * s) * scale;
    float v2 = (x1 * s + x2 * c) * scale;
    size_t o = ((size_t)(b * nh + hh) * Tt + t) * HD;
    __nv_bfloat16 h1 = __float2bfloat16(v1);
    __nv_bfloat16 h2 = __float2bfloat16(v2);
    H[o + f] = h1;      L[o + f]      = __float2bfloat16(v1 - __bfloat162float(h1));
    H[o + 64 + f] = h2; L[o + 64 + f] = __float2bfloat16(v2 - __bfloat162float(h2));
}

// split + permute (no rope): for V
__global__ void split_perm_kernel(const float* __restrict__ src,
                                  __nv_bfloat16* __restrict__ H,
                                  __nv_bfloat16* __restrict__ L,
                                  int nh, int colbase, int sstride)
{
    size_t idx = (size_t)blockIdx.x * blockDim.x + threadIdx.x;
    int d = idx & (HD - 1);
    size_t r = idx >> 7;
    int hh = r % nh;
    size_t bt = r / nh;
    int t = bt % Tt;
    int b = bt / Tt;
    float v = src[bt * sstride + colbase + hh * HD + d];
    __nv_bfloat16 hi = __float2bfloat16(v);
    size_t o = ((size_t)(b * nh + hh) * Tt + t) * HD + d;
    H[o] = hi;
    L[o] = __float2bfloat16(v - __bfloat162float(hi));
}

// ---------------- mma.sync bf16x3 GEMM, 2-stage, 2 CTAs/SM ----------------
#define KSP 40
#define TILE_B (128 * KSP * 2)       // 10240
#define STAGE_B (4 * TILE_B)         // 40960
#define GEMM_SMEM (2 * STAGE_B)      // 81920

__global__ void __launch_bounds__(256, 2) mma_gemm(
    const __nv_bfloat16* __restrict__ Ah, const __nv_bfloat16* __restrict__ Al,
    const __nv_bfloat16* __restrict__ Bh, const __nv_bfloat16* __restrict__ Bl,
    float* __restrict__ C, int M, int N, int K)
{
    extern __shared__ char sm[];
    uint32_t smem_base = smem_u32(sm);
    int tid = threadIdx.x;
    int wid = tid >> 5, lane = tid & 31;
    int wm = wid >> 2, wn = wid & 3;

    int m0 = blockIdx.y * 128, n0 = blockIdx.x * 128;
    int nstage = K / 32;

    float acc[4][4][4];
#pragma unroll
    for (int a = 0; a < 4; a++)
#pragma unroll
        for (int b = 0; b < 4; b++)
#pragma unroll
            for (int c = 0; c < 4; c++) acc[a][b][c] = 0.f;

    auto load_stage = [&](int kc, int s) {
        int kcol = kc * 32;
        uint32_t sb = smem_base + s * STAGE_B;
#pragma unroll
        for (int i = 0; i < 8; i++) {
            int c = tid + i * 256;
            int tile = c >> 9;
            int cid = c & 511;
            int row = cid >> 2;
            int kch = cid & 3;
            const __nv_bfloat16* src;
            if (tile == 0)      src = Ah + (size_t)(m0 + row) * K + kcol + kch * 8;
            else if (tile == 1) src = Al + (size_t)(m0 + row) * K + kcol + kch * 8;
            else if (tile == 2) src = Bh + (size_t)(n0 + row) * K + kcol + kch * 8;
            else                src = Bl + (size_t)(n0 + row) * K + kcol + kch * 8;
            uint32_t dst = sb + tile * TILE_B + (row * KSP + kch * 8) * 2;
            CP_ASYNC16(dst, src);
        }
    };

    load_stage(0, 0); CP_COMMIT();

    uint32_t aoff = ((wm * 64 + (lane & 15)) * KSP + ((lane >> 4) << 3)) * 2;
    uint32_t boff = ((wn * 32 + ((lane >> 4) << 3) + (lane & 7)) * KSP + (((lane >> 3) & 1) << 3)) * 2;

    for (int kc = 0; kc < nstage; kc++) {
        CP_WAIT0();
        __syncthreads();
        if (kc + 1 < nstage) { load_stage(kc + 1, (kc + 1) & 1); CP_COMMIT(); }

        uint32_t sb = smem_base + (kc & 1) * STAGE_B;
        uint32_t aHi = sb + aoff;
        uint32_t bHi = sb + 2 * TILE_B + boff;

#pragma unroll
        for (int kk = 0; kk < 2; kk++) {
            uint32_t ko = kk * 32;
            uint32_t bh[2][4], bl[2][4];
#pragma unroll
            for (int pr = 0; pr < 2; pr++) {
                LDSM_X4(bh[pr][0], bh[pr][1], bh[pr][2], bh[pr][3], bHi + pr * 16 * KSP * 2 + ko);
                LDSM_X4(bl[pr][0], bl[pr][1], bl[pr][2], bl[pr][3], bHi + TILE_B + pr * 16 * KSP * 2 + ko);
            }
#pragma unroll
            for (int mt = 0; mt < 4; mt++) {
                uint32_t ah4[4], al4[4];
                LDSM_X4(ah4[0], ah4[1], ah4[2], ah4[3], aHi + mt * 16 * KSP * 2 + ko);
                LDSM_X4(al4[0], al4[1], al4[2], al4[3], aHi + TILE_B + mt * 16 * KSP * 2 + ko);
#pragma unroll
                for (int nt = 0; nt < 4; nt++) {
                    int pr = nt >> 1, ix = (nt & 1) * 2;
                    MMA16816(acc[mt][nt], ah4, bh[pr][ix], bh[pr][ix + 1]);
                    MMA16816(acc[mt][nt], ah4, bl[pr][ix], bl[pr][ix + 1]);
                    MMA16816(acc[mt][nt], al4, bh[pr][ix], bh[pr][ix + 1]);
                }
            }
        }
    }

#pragma unroll
    for (int mt = 0; mt < 4; mt++)
#pragma unroll
        for (int nt = 0; nt < 4; nt++) {
            int row = m0 + wm * 64 + mt * 16 + (lane >> 2);
            int col = n0 + wn * 32 + nt * 8 + (lane & 3) * 2;
            *(float2*)&C[(size_t)row * N + col]       = make_float2(acc[mt][nt][0], acc[mt][nt][1]);
            *(float2*)&C[(size_t)(row + 8) * N + col] = make_float2(acc[mt][nt][2], acc[mt][nt][3]);
        }
}

// ---------------- Flash attention: Bq=128, double-buffered KV ----------------
#define FSTR 136
#define FTB  (64 * FSTR * 2)         // KV tile: 17408
#define QTB  (128 * FSTR * 2)        // Q tile:  34816
#define KVST (4 * FTB)               // one KV stage: 69632
#define FLASH_SMEM (2 * QTB + 2 * KVST)   // 208896

__global__ void __launch_bounds__(256) flash_mma(
    const __nv_bfloat16* __restrict__ Qh, const __nv_bfloat16* __restrict__ Ql,
    const __nv_bfloat16* __restrict__ Kh, const __nv_bfloat16* __restrict__ Kl,
    const __nv_bfloat16* __restrict__ Vh, const __nv_bfloat16* __restrict__ Vl,
    __nv_bfloat16* __restrict__ Oh, __nv_bfloat16* __restrict__ Ol)
{
    extern __shared__ char sm[];
    uint32_t sb = smem_u32(sm);
    int tid = threadIdx.x, lane = tid & 31, wm = tid >> 5;
    int qt = gridDim.x - 1 - blockIdx.x;      // longest CTAs first
    int h = blockIdx.y, b = blockIdx.z;
    int q0 = qt * 128;
    int kvh = h / GQ;

    const __nv_bfloat16* Qhp = Qh + ((size_t)(b * Hh + h) * Tt + q0) * HD;
    const __nv_bfloat16* Qlp = Ql + ((size_t)(b * Hh + h) * Tt + q0) * HD;
    const __nv_bfloat16* Khp = Kh + (size_t)(b * KVh + kvh) * Tt * HD;
    const __nv_bfloat16* Klp = Kl + (size_t)(b * KVh + kvh) * Tt * HD;
    const __nv_bfloat16* Vhp = Vh + (size_t)(b * KVh + kvh) * Tt * HD;
    const __nv_bfloat16* Vlp = Vl + (size_t)(b * KVh + kvh) * Tt * HD;

    // Q tiles -> smem (128 rows, hi+lo)
#pragma unroll
    for (int i = 0; i < 8; i++) {
        int ch = tid + i * 256;
        int r = ch >> 4, c = ch & 15;
        uint32_t off = (uint32_t)(r * FSTR + c * 8) * 2;
        CP_ASYNC16(sb + off,       Qhp + (size_t)r * HD + c * 8);
        CP_ASYNC16(sb + QTB + off, Qlp + (size_t)r * HD + c * 8);
    }

    auto load_kv = [&](int j, int s) {
        uint32_t kb = sb + 2 * QTB + s * KVST;
        const __nv_bfloat16* kh = Khp + (size_t)j * 64 * HD;
        const __nv_bfloat16* kl = Klp + (size_t)j * 64 * HD;
        const __nv_bfloat16* vh = Vhp + (size_t)j * 64 * HD;
        const __nv_bfloat16* vl = Vlp + (size_t)j * 64 * HD;
#pragma unroll
        for (int i = 0; i < 4; i++) {
            int ch = tid + i * 256;
            int r = ch >> 4, c = ch & 15;
            uint32_t off = (uint32_t)(r * FSTR + c * 8) * 2;
            size_t go = (size_t)r * HD + c * 8;
            CP_ASYNC16(kb + off,           kh + go);
            CP_ASYNC16(kb + FTB + off,     kl + go);
            CP_ASYNC16(kb + 2 * FTB + off, vh + go);
            CP_ASYNC16(kb + 3 * FTB + off, vl + go);
        }
    };

    load_kv(0, 0);
    CP_COMMIT();

    float oc[16][4];
#pragma unroll
    for (int i = 0; i < 16; i++)
#pragma unroll
        for (int e = 0; e < 4; e++) oc[i][e] = 0.f;
    float mrow[2] = { -1e30f, -1e30f };
    float lrow[2] = { 0.f, 0.f };

    uint32_t q_add = (uint32_t)((wm * 16 + (lane & 15)) * FSTR + ((lane >> 4) << 3)) * 2;
    uint32_t k_add = (uint32_t)(((lane >> 4) * 8 + (lane & 7)) * FSTR + (((lane >> 3) & 1) << 3)) * 2;
    int vg = lane >> 3, vl8 = lane & 7;
    uint32_t v_add = (uint32_t)(((vg & 1) * 8 + vl8) * FSTR + ((vg >> 1) << 3)) * 2;

    int ntile = 2 * qt + 2;
    for (int j = 0; j < ntile; j++) {
        CP_WAIT0();
        __syncthreads();
        if (j + 1 < ntile) { load_kv(j + 1, (j + 1) & 1); CP_COMMIT(); }

        uint32_t kvb = sb + 2 * QTB + (j & 1) * KVST;

        // ---- S = Q @ K^T ----
        float sc[8][4];
#pragma unroll
        for (int nt = 0; nt < 8; nt++)
#pragma unroll
            for (int e = 0; e < 4; e++) sc[nt][e] = 0.f;

#pragma unroll
        for (int kb = 0; kb < 8; kb++) {
            uint32_t qh4[4], ql4[4];
            uint32_t ko = kb * 32;
            LDSM_X4(qh4[0], qh4[1], qh4[2], qh4[3], sb + q_add + ko);
            LDSM_X4(ql4[0], ql4[1], ql4[2], ql4[3], sb + QTB + q_add + ko);
            uint32_t kh4[4][4], kl4[4][4];
#pragma unroll
            for (int pr = 0; pr < 4; pr++) {
                uint32_t ra = pr * 16 * FSTR * 2 + ko;
                LDSM_X4(kh4[pr][0], kh4[pr][1], kh4[pr][2], kh4[pr][3], kvb + k_add + ra);
                LDSM_X4(kl4[pr][0], kl4[pr][1], kl4[pr][2], kl4[pr][3], kvb + FTB + k_add + ra);
            }
#pragma unroll
            for (int nt = 0; nt < 8; nt++) {
                int pr = nt >> 1, ix = (nt & 1) * 2;
                MMA16816(sc[nt], qh4, kh4[pr][ix], kh4[pr][ix + 1]);
                MMA16816(sc[nt], qh4, kl4[pr][ix], kl4[pr][ix + 1]);
                MMA16816(sc[nt], ql4, kh4[pr][ix], kh4[pr][ix + 1]);
            }
        }

        // ---- causal mask (last two tiles) ----
        if (j >= ntile - 2) {
            int row0 = q0 + wm * 16 + (lane >> 2);
#pragma unroll
            for (int nt = 0; nt < 8; nt++) {
                int col = j * 64 + nt * 8 + (lane & 3) * 2;
#pragma unroll
                for (int e = 0; e < 4; e++) {
                    int cc = col + (e & 1);
                    int rr = row0 + ((e >> 1) << 3);
                    if (cc > rr) sc[nt][e] = -1e30f;
                }
            }
        }

        // ---- online softmax ----
#pragma unroll
        for (int half = 0; half < 2; half++) {
            int e0 = half * 2;
            float mx = -1e30f;
#pragma unroll
            for (int nt = 0; nt < 8; nt++)
                mx = fmaxf(mx, fmaxf(sc[nt][e0], sc[nt][e0 + 1]));
            mx = fmaxf(mx, __shfl_xor_sync(0xffffffff, mx, 1));
            mx = fmaxf(mx, __shfl_xor_sync(0xffffffff, mx, 2));
            float mnew = fmaxf(mrow[half], mx);
            float alpha = __expf(mrow[half] - mnew);
            float sum = 0.f;
#pragma unroll
            for (int nt = 0; nt < 8; nt++) {
                float p0 = __expf(sc[nt][e0]     - mnew);
                float p1 = __expf(sc[nt][e0 + 1] - mnew);
                sc[nt][e0] = p0; sc[nt][e0 + 1] = p1;
                sum += p0 + p1;
            }
            sum += __shfl_xor_sync(0xffffffff, sum, 1);
            sum += __shfl_xor_sync(0xffffffff, sum, 2);
            lrow[half] = lrow[half] * alpha + sum;
            mrow[half] = mnew;
#pragma unroll
            for (int nt = 0; nt < 16; nt++) {
                oc[nt][e0]     *= alpha;
                oc[nt][e0 + 1] *= alpha;
            }
        }

        // ---- O += P @ V ----
#pragma unroll
        for (int kb2 = 0; kb2 < 4; kb2++) {
            int nt0 = kb2 * 2, nt1 = nt0 + 1;
            uint32_t ph[4], pl[4];
#pragma unroll
            for (int r4 = 0; r4 < 4; r4++) {
                int nts = (r4 >> 1) ? nt1 : nt0;
                int eb = (r4 & 1) * 2;
                float x0 = sc[nts][eb], x1 = sc[nts][eb + 1];
                __nv_bfloat16 h0 = __float2bfloat16(x0);
                __nv_bfloat16 h1 = __float2bfloat16(x1);
                ph[r4] = packbf2(h0, h1);
                pl[r4] = packbf2(__float2bfloat16(x0 - __bfloat162float(h0)),
                                 __float2bfloat16(x1 - __bfloat162float(h1)));
            }
            uint32_t vrow = kb2 * 16 * FSTR * 2;
#pragma unroll
            for (int np = 0; np < 8; np++) {
                uint32_t va = kvb + 2 * FTB + v_add + vrow + np * 32;
                uint32_t vb2 = va + FTB;
                uint32_t v4h[4], v4l[4];
                LDSM_X4T(v4h[0], v4h[1], v4h[2], v4h[3], va);
                LDSM_X4T(v4l[0], v4l[1], v4l[2], v4l[3], vb2);
                int nt = np * 2;
                MMA16816(oc[nt], ph, v4h[0], v4h[1]);
                MMA16816(oc[nt], ph, v4l[0], v4l[1]);
                MMA16816(oc[nt], pl, v4h[0], v4h[1]);
                MMA16816(oc[nt + 1], ph, v4h[2], v4h[3]);
                MMA16816(oc[nt + 1], ph, v4l[2], v4l[3]);
                MMA16816(oc[nt + 1], pl, v4h[2], v4h[3]);
            }
        }
    }

    // ---- epilogue: normalize, split, write [B,T,H,HD] ----
#pragma unroll
    for (int half = 0; half < 2; half++) {
        float inv_l = 1.0f / lrow[half];
        int row = q0 + wm * 16 + (lane >> 2) + half * 8;
        size_t ob = (((size_t)b * Tt + row) * Hh + h) * HD;
#pragma unroll
        for (int nt = 0; nt < 16; nt++) {
            int d = nt * 8 + (lane & 3) * 2;
            float v0 = oc[nt][half * 2] * inv_l;
            float v1 = oc[nt][half * 2 + 1] * inv_l;
            __nv_bfloat16 h0 = __float2bfloat16(v0);
            __nv_bfloat16 h1 = __float2bfloat16(v1);
            *(__nv_bfloat162*)&Oh[ob + d] = __nv_bfloat162(h0, h1);
            *(__nv_bfloat162*)&Ol[ob + d] = __nv_bfloat162(
                __float2bfloat16(v0 - __bfloat162float(h0)),
                __float2bfloat16(v1 - __bfloat162float(h1)));
        }
    }
}

// ---------------- launch ----------------
extern "C" void kernel_launch(void* const* d_in, const int* in_sizes, int n_in,
                              void* d_out, int out_size)
{
    const float* x  = (const float*)d_in[0];
    const float* Wq = (const float*)d_in[1];
    const float* Wk = (const float*)d_in[2];
    const float* Wv = (const float*)d_in[3];
    const float* Wo = (const float*)d_in[4];
    float* out = (float*)d_out;

    float* qkv;
    cudaGetSymbolAddress((void**)&qkv, g_qkv);
    __nv_bfloat16 *xsh, *xsl, *osh, *osl, *wqkvh, *wqkvl, *woh, *wol;
    __nv_bfloat16 *qh, *ql, *kh, *kl, *vh, *vl;
    cudaGetSymbolAddress((void**)&xsh, g_xs_h);
    cudaGetSymbolAddress((void**)&xsl, g_xs_l);
    cudaGetSymbolAddress((void**)&osh, g_os_h);
    cudaGetSymbolAddress((void**)&osl, g_os_l);
    cudaGetSymbolAddress((void**)&wqkvh, g_wqkvt_h);
    cudaGetSymbolAddress((void**)&wqkvl, g_wqkvt_l);
    cudaGetSymbolAddress((void**)&woh, g_wot_h);
    cudaGetSymbolAddress((void**)&wol, g_wot_l);
    cudaGetSymbolAddress((void**)&qh, g_qh);
    cudaGetSymbolAddress((void**)&ql, g_ql);
    cudaGetSymbolAddress((void**)&kh, g_kh);
    cudaGetSymbolAddress((void**)&kl, g_kl);
    cudaGetSymbolAddress((void**)&vh, g_vh);
    cudaGetSymbolAddress((void**)&vl, g_vl);

    const int M = Bsz * Tt;   // 4096
    const int n4 = M * Dd / 4;

    cudaFuncSetAttribute(mma_gemm, cudaFuncAttributeMaxDynamicSharedMemorySize, GEMM_SMEM);
    cudaFuncSetAttribute(flash_mma, cudaFuncAttributeMaxDynamicSharedMemorySize, FLASH_SMEM);

    // conversions: x split; weights transposed+split (QKV concatenated by rows)
    split_kernel<<<4096, 256>>>(x, xsh, xsl, n4);
    tsplit_kernel<<<dim3(Dd/32, Dd/32), dim3(32,8)>>>(Wq, wqkvh, wqkvl, Dd, Dd);
    tsplit_kernel<<<dim3((KVh*HD)/32, Dd/32), dim3(32,8)>>>(Wk, wqkvh + (size_t)2048*Dd, wqkvl + (size_t)2048*Dd, Dd, KVh*HD);
    tsplit_kernel<<<dim3((KVh*HD)/32, Dd/32), dim3(32,8)>>>(Wv, wqkvh + (size_t)2560*Dd, wqkvl + (size_t)2560*Dd, Dd, KVh*HD);
    tsplit_kernel<<<dim3(Dd/32, Dd/32), dim3(32,8)>>>(Wo, woh, wol, Dd, Dd);

    // fused QKV projection
    mma_gemm<<<dim3(NQKV/128, M/128), 256, GEMM_SMEM>>>(xsh, xsl, wqkvh, wqkvl, qkv, M, NQKV, Dd);

    // RoPE + split + permute (Q scaled), V split + permute
    const float scale = 0.08838834764831845f;
    rope_split_kernel<<<(Bsz*Tt*Hh)/2, 128>>>(qkv, qh, ql, Hh, 0, NQKV, scale);
    rope_split_kernel<<<(Bsz*Tt*KVh)/2, 128>>>(qkv, kh, kl, KVh, 2048, NQKV, 1.0f);
    split_perm_kernel<<<(Bsz*Tt*KVh*HD)/256, 256>>>(qkv, vh, vl, KVh, 2560, NQKV);

    // flash attention (tensor cores, split-bf16 output)
    flash_mma<<<dim3(Tt/128, Hh, Bsz), 256, FLASH_SMEM>>>(qh, ql, kh, kl, vh, vl, osh, osl);

    // output projection
    mma_gemm<<<dim3(Dd/128, M/128), 256, GEMM_SMEM>>>(osh, osl, woh, wol, out, M, Dd, Dd);
}

// round 6
// speedup vs baseline: 4.9964x; 1.0028x over previous
#include <cuda_runtime.h>
#include <cuda_bf16.h>
#include <cstdint>
#include <math.h>

#define Bsz 2
#define Tt 2048
#define Dd 2048
#define Hh 16
#define KVh 4
#define HD 128
#define GQ (Hh/KVh)
#define NQKV 3072

// ---------------- scratch ----------------
__device__ __nv_bfloat16 g_xs_h[(size_t)Bsz*Tt*Dd];
__device__ __nv_bfloat16 g_xs_l[(size_t)Bsz*Tt*Dd];
__device__ __nv_bfloat16 g_os_h[(size_t)Bsz*Tt*Dd];
__device__ __nv_bfloat16 g_os_l[(size_t)Bsz*Tt*Dd];
__device__ __nv_bfloat16 g_wqkvt_h[(size_t)NQKV*Dd];
__device__ __nv_bfloat16 g_wqkvt_l[(size_t)NQKV*Dd];
__device__ __nv_bfloat16 g_wot_h[(size_t)Dd*Dd];
__device__ __nv_bfloat16 g_wot_l[(size_t)Dd*Dd];

__device__ __nv_bfloat16 g_qh[(size_t)Bsz*Hh*Tt*HD];
__device__ __nv_bfloat16 g_ql[(size_t)Bsz*Hh*Tt*HD];
__device__ __nv_bfloat16 g_kh[(size_t)Bsz*KVh*Tt*HD];
__device__ __nv_bfloat16 g_kl[(size_t)Bsz*KVh*Tt*HD];
__device__ __nv_bfloat16 g_vh[(size_t)Bsz*KVh*Tt*HD];
__device__ __nv_bfloat16 g_vl[(size_t)Bsz*KVh*Tt*HD];

__device__ float2 g_rope[(size_t)Tt*64];   // (sin, cos) per (t, f)

// ---------------- helpers ----------------
__device__ __forceinline__ uint32_t smem_u32(const void* p) {
    uint32_t a;
    asm("{ .reg .u64 t; cvta.to.shared.u64 t, %1; cvt.u32.u64 %0, t; }" : "=r"(a) : "l"(p));
    return a;
}

#define CP_ASYNC16(dst, src) \
    asm volatile("cp.async.cg.shared.global [%0], [%1], 16;" :: "r"(dst), "l"(src))
#define CP_COMMIT() asm volatile("cp.async.commit_group;")
#define CP_WAIT0()  asm volatile("cp.async.wait_group 0;")

#define LDSM_X4(r0, r1, r2, r3, addr) \
    asm volatile("ldmatrix.sync.aligned.m8n8.x4.shared.b16 {%0,%1,%2,%3}, [%4];" \
        : "=r"(r0), "=r"(r1), "=r"(r2), "=r"(r3) : "r"(addr))

#define LDSM_X4T(r0, r1, r2, r3, addr) \
    asm volatile("ldmatrix.sync.aligned.m8n8.x4.trans.shared.b16 {%0,%1,%2,%3}, [%4];" \
        : "=r"(r0), "=r"(r1), "=r"(r2), "=r"(r3) : "r"(addr))

#define MMA16816(c, a, b0, b1) \
    asm volatile("mma.sync.aligned.m16n8k16.row.col.f32.bf16.bf16.f32 " \
        "{%0,%1,%2,%3},{%4,%5,%6,%7},{%8,%9},{%0,%1,%2,%3};" \
        : "+f"((c)[0]), "+f"((c)[1]), "+f"((c)[2]), "+f"((c)[3]) \
        : "r"((a)[0]), "r"((a)[1]), "r"((a)[2]), "r"((a)[3]), "r"(b0), "r"(b1))

__device__ __forceinline__ uint32_t packbf2(__nv_bfloat16 lo, __nv_bfloat16 hi) {
    union { __nv_bfloat162 v; uint32_t u; } cv;
    cv.v.x = lo; cv.v.y = hi;
    return cv.u;
}

// ---------------- conversion kernels ----------------
__global__ void split_kernel(const float* __restrict__ A,
                             __nv_bfloat16* __restrict__ H,
                             __nv_bfloat16* __restrict__ L, int n4)
{
    int i = blockIdx.x * blockDim.x + threadIdx.x;
    int stride = gridDim.x * blockDim.x;
    for (; i < n4; i += stride) {
        float4 a = ((const float4*)A)[i];
        __nv_bfloat16 h0 = __float2bfloat16(a.x);
        __nv_bfloat16 h1 = __float2bfloat16(a.y);
        __nv_bfloat16 h2 = __float2bfloat16(a.z);
        __nv_bfloat16 h3 = __float2bfloat16(a.w);
        __nv_bfloat16 l0 = __float2bfloat16(a.x - __bfloat162float(h0));
        __nv_bfloat16 l1 = __float2bfloat16(a.y - __bfloat162float(h1));
        __nv_bfloat16 l2 = __float2bfloat16(a.z - __bfloat162float(h2));
        __nv_bfloat16 l3 = __float2bfloat16(a.w - __bfloat162float(h3));
        ((__nv_bfloat162*)H)[2*i]   = __nv_bfloat162(h0, h1);
        ((__nv_bfloat162*)H)[2*i+1] = __nv_bfloat162(h2, h3);
        ((__nv_bfloat162*)L)[2*i]   = __nv_bfloat162(l0, l1);
        ((__nv_bfloat162*)L)[2*i+1] = __nv_bfloat162(l2, l3);
    }
}

// all four W[K,N] fp32 -> Wt_hi/lo[N,K] bf16 in one launch (z selects tensor)
__global__ void tsplit_all_kernel(
    const float* __restrict__ Wq, const float* __restrict__ Wk,
    const float* __restrict__ Wv, const float* __restrict__ Wo,
    __nv_bfloat16* __restrict__ QKVh, __nv_bfloat16* __restrict__ QKVl,
    __nv_bfloat16* __restrict__ Oh,   __nv_bfloat16* __restrict__ Ol)
{
    __shared__ float t[32][33];
    int z = blockIdx.z;
    const float* W;
    __nv_bfloat16 *Th, *Tl;
    int N;
    if (z == 0)      { W = Wq; Th = QKVh;                      Tl = QKVl;                      N = 2048; }
    else if (z == 1) { W = Wk; Th = QKVh + (size_t)2048 * Dd;  Tl = QKVl + (size_t)2048 * Dd;  N = 512; }
    else if (z == 2) { W = Wv; Th = QKVh + (size_t)2560 * Dd;  Tl = QKVl + (size_t)2560 * Dd;  N = 512; }
    else             { W = Wo; Th = Oh;                        Tl = Ol;                        N = 2048; }
    int n0 = blockIdx.x * 32, k0 = blockIdx.y * 32;
    if (n0 >= N) return;
    const int K = Dd;
    int tx = threadIdx.x, ty0 = threadIdx.y;
#pragma unroll
    for (int j = 0; j < 4; j++) {
        int ty = ty0 + j * 8;
        t[ty][tx] = W[(size_t)(k0 + ty) * N + n0 + tx];
    }
    __syncthreads();
#pragma unroll
    for (int j = 0; j < 4; j++) {
        int ty = ty0 + j * 8;
        float v = t[tx][ty];
        size_t o = (size_t)(n0 + ty) * K + k0 + tx;
        __nv_bfloat16 h = __float2bfloat16(v);
        Th[o] = h;
        Tl[o] = __float2bfloat16(v - __bfloat162float(h));
    }
}

// rope table: (t, f) -> (sin, cos)
__global__ void rope_table_kernel(float2* __restrict__ tab)
{
    int i = blockIdx.x * blockDim.x + threadIdx.x;   // t*64 + f
    int f = i & 63;
    int t = i >> 6;
    float inv = powf(10000.0f, -(float)f * (1.0f / 64.0f));
    float s, c;
    sincosf((float)t * inv, &s, &c);
    tab[i] = make_float2(s, c);
}

// ---------------- mma.sync bf16x3 GEMM, 2-stage, 2 CTAs/SM ----------------
// mode 0: C fp32 plain. mode 1: fused QKV epilogue (RoPE + split + permute).
#define KSP 40
#define TILE_B (128 * KSP * 2)       // 10240
#define STAGE_B (4 * TILE_B)         // 40960
#define GEMM_SMEM (2 * STAGE_B)      // 81920

__global__ void __launch_bounds__(256, 2) mma_gemm(
    const __nv_bfloat16* __restrict__ Ah, const __nv_bfloat16* __restrict__ Al,
    const __nv_bfloat16* __restrict__ Bh, const __nv_bfloat16* __restrict__ Bl,
    float* __restrict__ C, int M, int N, int K, int mode,
    const float2* __restrict__ rope,
    __nv_bfloat16* __restrict__ QH, __nv_bfloat16* __restrict__ QL,
    __nv_bfloat16* __restrict__ KH, __nv_bfloat16* __restrict__ KL,
    __nv_bfloat16* __restrict__ VH, __nv_bfloat16* __restrict__ VL)
{
    extern __shared__ char sm[];
    uint32_t smem_base = smem_u32(sm);
    int tid = threadIdx.x;
    int wid = tid >> 5, lane = tid & 31;
    int wm = wid >> 2, wn = wid & 3;

    int m0 = blockIdx.y * 128, n0 = blockIdx.x * 128;
    int nstage = K / 32;

    float acc[4][4][4];
#pragma unroll
    for (int a = 0; a < 4; a++)
#pragma unroll
        for (int b = 0; b < 4; b++)
#pragma unroll
            for (int c = 0; c < 4; c++) acc[a][b][c] = 0.f;

    auto load_stage = [&](int kc, int s) {
        int kcol = kc * 32;
        uint32_t sb = smem_base + s * STAGE_B;
#pragma unroll
        for (int i = 0; i < 8; i++) {
            int c = tid + i * 256;
            int tile = c >> 9;
            int cid = c & 511;
            int row = cid >> 2;
            int kch = cid & 3;
            const __nv_bfloat16* src;
            if (tile == 0)      src = Ah + (size_t)(m0 + row) * K + kcol + kch * 8;
            else if (tile == 1) src = Al + (size_t)(m0 + row) * K + kcol + kch * 8;
            else if (tile == 2) src = Bh + (size_t)(n0 + row) * K + kcol + kch * 8;
            else                src = Bl + (size_t)(n0 + row) * K + kcol + kch * 8;
            uint32_t dst = sb + tile * TILE_B + (row * KSP + kch * 8) * 2;
            CP_ASYNC16(dst, src);
        }
    };

    load_stage(0, 0); CP_COMMIT();

    uint32_t aoff = ((wm * 64 + (lane & 15)) * KSP + ((lane >> 4) << 3)) * 2;
    uint32_t boff = ((wn * 32 + ((lane >> 4) << 3) + (lane & 7)) * KSP + (((lane >> 3) & 1) << 3)) * 2;

    for (int kc = 0; kc < nstage; kc++) {
        CP_WAIT0();
        __syncthreads();
        if (kc + 1 < nstage) { load_stage(kc + 1, (kc + 1) & 1); CP_COMMIT(); }

        uint32_t sb = smem_base + (kc & 1) * STAGE_B;
        uint32_t aHi = sb + aoff;
        uint32_t bHi = sb + 2 * TILE_B + boff;

#pragma unroll
        for (int kk = 0; kk < 2; kk++) {
            uint32_t ko = kk * 32;
            uint32_t bh[2][4], bl[2][4];
#pragma unroll
            for (int pr = 0; pr < 2; pr++) {
                LDSM_X4(bh[pr][0], bh[pr][1], bh[pr][2], bh[pr][3], bHi + pr * 16 * KSP * 2 + ko);
                LDSM_X4(bl[pr][0], bl[pr][1], bl[pr][2], bl[pr][3], bHi + TILE_B + pr * 16 * KSP * 2 + ko);
            }
#pragma unroll
            for (int mt = 0; mt < 4; mt++) {
                uint32_t ah4[4], al4[4];
                LDSM_X4(ah4[0], ah4[1], ah4[2], ah4[3], aHi + mt * 16 * KSP * 2 + ko);
                LDSM_X4(al4[0], al4[1], al4[2], al4[3], aHi + TILE_B + mt * 16 * KSP * 2 + ko);
#pragma unroll
                for (int nt = 0; nt < 4; nt++) {
                    int pr = nt >> 1, ix = (nt & 1) * 2;
                    MMA16816(acc[mt][nt], ah4, bh[pr][ix], bh[pr][ix + 1]);
                    MMA16816(acc[mt][nt], ah4, bl[pr][ix], bl[pr][ix + 1]);
                    MMA16816(acc[mt][nt], al4, bh[pr][ix], bh[pr][ix + 1]);
                }
            }
        }
    }

    if (mode == 0) {
#pragma unroll
        for (int mt = 0; mt < 4; mt++)
#pragma unroll
            for (int nt = 0; nt < 4; nt++) {
                int row = m0 + wm * 64 + mt * 16 + (lane >> 2);
                int col = n0 + wn * 32 + nt * 8 + (lane & 3) * 2;
                *(float2*)&C[(size_t)row * N + col]       = make_float2(acc[mt][nt][0], acc[mt][nt][1]);
                *(float2*)&C[(size_t)(row + 8) * N + col] = make_float2(acc[mt][nt][2], acc[mt][nt][3]);
            }
    } else {
        // fused QKV epilogue: RoPE (q,k) + split + permute to [B*nh, T, HD]
        const float qscale = 0.08838834764831845f;
#pragma unroll
        for (int mt = 0; mt < 4; mt++)
#pragma unroll
            for (int nt = 0; nt < 4; nt++) {
                int colp = n0 + wn * 32 + nt * 8 + (lane & 3) * 2;
#pragma unroll
                for (int rr = 0; rr < 2; rr++) {
                    int row = m0 + wm * 64 + mt * 16 + (lane >> 2) + rr * 8;
                    float x1 = acc[mt][nt][rr * 2];
                    float x2 = acc[mt][nt][rr * 2 + 1];
                    int t = row & (Tt - 1);
                    int b = row >> 11;
                    if (colp < 2048) {
                        int hh = colp >> 7, d = colp & 127, f = d >> 1;
                        float2 sc2 = rope[t * 64 + f];
                        float v1 = (x1 * sc2.y - x2 * sc2.x) * qscale;
                        float v2 = (x1 * sc2.x + x2 * sc2.y) * qscale;
                        size_t o = ((size_t)(b * Hh + hh) * Tt + t) * HD;
                        __nv_bfloat16 h1 = __float2bfloat16(v1);
                        __nv_bfloat16 h2 = __float2bfloat16(v2);
                        QH[o + f]      = h1;
                        QL[o + f]      = __float2bfloat16(v1 - __bfloat162float(h1));
                        QH[o + 64 + f] = h2;
                        QL[o + 64 + f] = __float2bfloat16(v2 - __bfloat162float(h2));
                    } else if (colp < 2560) {
                        int kvh = (colp - 2048) >> 7, d = (colp - 2048) & 127, f = d >> 1;
                        float2 sc2 = rope[t * 64 + f];
                        float v1 = x1 * sc2.y - x2 * sc2.x;
                        float v2 = x1 * sc2.x + x2 * sc2.y;
                        size_t o = ((size_t)(b * KVh + kvh) * Tt + t) * HD;
                        __nv_bfloat16 h1 = __float2bfloat16(v1);
                        __nv_bfloat16 h2 = __float2bfloat16(v2);
                        KH[o + f]      = h1;
                        KL[o + f]      = __float2bfloat16(v1 - __bfloat162float(h1));
                        KH[o + 64 + f] = h2;
                        KL[o + 64 + f] = __float2bfloat16(v2 - __bfloat162float(h2));
                    } else {
                        int kvh = (colp - 2560) >> 7, d = (colp - 2560) & 127;
                        size_t o = ((size_t)(b * KVh + kvh) * Tt + t) * HD + d;
                        __nv_bfloat16 h1 = __float2bfloat16(x1);
                        __nv_bfloat16 h2 = __float2bfloat16(x2);
                        *(__nv_bfloat162*)&VH[o] = __nv_bfloat162(h1, h2);
                        *(__nv_bfloat162*)&VL[o] = __nv_bfloat162(
                            __float2bfloat16(x1 - __bfloat162float(h1)),
                            __float2bfloat16(x2 - __bfloat162float(h2)));
                    }
                }
            }
    }
}

// ---------------- Flash attention: Bq=128, double-buffered KV ----------------
#define FSTR 136
#define FTB  (64 * FSTR * 2)
#define QTB  (128 * FSTR * 2)
#define KVST (4 * FTB)
#define FLASH_SMEM (2 * QTB + 2 * KVST)   // 208896

__global__ void __launch_bounds__(256) flash_mma(
    const __nv_bfloat16* __restrict__ Qh, const __nv_bfloat16* __restrict__ Ql,
    const __nv_bfloat16* __restrict__ Kh, const __nv_bfloat16* __restrict__ Kl,
    const __nv_bfloat16* __restrict__ Vh, const __nv_bfloat16* __restrict__ Vl,
    __nv_bfloat16* __restrict__ Oh, __nv_bfloat16* __restrict__ Ol)
{
    extern __shared__ char sm[];
    uint32_t sb = smem_u32(sm);
    int tid = threadIdx.x, lane = tid & 31, wm = tid >> 5;
    int qt = gridDim.x - 1 - blockIdx.x;
    int h = blockIdx.y, b = blockIdx.z;
    int q0 = qt * 128;
    int kvh = h / GQ;

    const __nv_bfloat16* Qhp = Qh + ((size_t)(b * Hh + h) * Tt + q0) * HD;
    const __nv_bfloat16* Qlp = Ql + ((size_t)(b * Hh + h) * Tt + q0) * HD;
    const __nv_bfloat16* Khp = Kh + (size_t)(b * KVh + kvh) * Tt * HD;
    const __nv_bfloat16* Klp = Kl + (size_t)(b * KVh + kvh) * Tt * HD;
    const __nv_bfloat16* Vhp = Vh + (size_t)(b * KVh + kvh) * Tt * HD;
    const __nv_bfloat16* Vlp = Vl + (size_t)(b * KVh + kvh) * Tt * HD;

#pragma unroll
    for (int i = 0; i < 8; i++) {
        int ch = tid + i * 256;
        int r = ch >> 4, c = ch & 15;
        uint32_t off = (uint32_t)(r * FSTR + c * 8) * 2;
        CP_ASYNC16(sb + off,       Qhp + (size_t)r * HD + c * 8);
        CP_ASYNC16(sb + QTB + off, Qlp + (size_t)r * HD + c * 8);
    }

    auto load_kv = [&](int j, int s) {
        uint32_t kb = sb + 2 * QTB + s * KVST;
        const __nv_bfloat16* kh = Khp + (size_t)j * 64 * HD;
        const __nv_bfloat16* kl = Klp + (size_t)j * 64 * HD;
        const __nv_bfloat16* vh = Vhp + (size_t)j * 64 * HD;
        const __nv_bfloat16* vl = Vlp + (size_t)j * 64 * HD;
#pragma unroll
        for (int i = 0; i < 4; i++) {
            int ch = tid + i * 256;
            int r = ch >> 4, c = ch & 15;
            uint32_t off = (uint32_t)(r * FSTR + c * 8) * 2;
            size_t go = (size_t)r * HD + c * 8;
            CP_ASYNC16(kb + off,           kh + go);
            CP_ASYNC16(kb + FTB + off,     kl + go);
            CP_ASYNC16(kb + 2 * FTB + off, vh + go);
            CP_ASYNC16(kb + 3 * FTB + off, vl + go);
        }
    };

    load_kv(0, 0);
    CP_COMMIT();

    float oc[16][4];
#pragma unroll
    for (int i = 0; i < 16; i++)
#pragma unroll
        for (int e = 0; e < 4; e++) oc[i][e] = 0.f;
    float mrow[2] = { -1e30f, -1e30f };
    float lrow[2] = { 0.f, 0.f };

    uint32_t q_add = (uint32_t)((wm * 16 + (lane & 15)) * FSTR + ((lane >> 4) << 3)) * 2;
    uint32_t k_add = (uint32_t)(((lane >> 4) * 8 + (lane & 7)) * FSTR + (((lane >> 3) & 1) << 3)) * 2;
    int vg = lane >> 3, vl8 = lane & 7;
    uint32_t v_add = (uint32_t)(((vg & 1) * 8 + vl8) * FSTR + ((vg >> 1) << 3)) * 2;

    int ntile = 2 * qt + 2;
    for (int j = 0; j < ntile; j++) {
        CP_WAIT0();
        __syncthreads();
        if (j + 1 < ntile) { load_kv(j + 1, (j + 1) & 1); CP_COMMIT(); }

        uint32_t kvb = sb + 2 * QTB + (j & 1) * KVST;

        float sc[8][4];
#pragma unroll
        for (int nt = 0; nt < 8; nt++)
#pragma unroll
            for (int e = 0; e < 4; e++) sc[nt][e] = 0.f;

#pragma unroll
        for (int kb = 0; kb < 8; kb++) {
            uint32_t qh4[4], ql4[4];
            uint32_t ko = kb * 32;
            LDSM_X4(qh4[0], qh4[1], qh4[2], qh4[3], sb + q_add + ko);
            LDSM_X4(ql4[0], ql4[1], ql4[2], ql4[3], sb + QTB + q_add + ko);
            uint32_t kh4[4][4], kl4[4][4];
#pragma unroll
            for (int pr = 0; pr < 4; pr++) {
                uint32_t ra = pr * 16 * FSTR * 2 + ko;
                LDSM_X4(kh4[pr][0], kh4[pr][1], kh4[pr][2], kh4[pr][3], kvb + k_add + ra);
                LDSM_X4(kl4[pr][0], kl4[pr][1], kl4[pr][2], kl4[pr][3], kvb + FTB + k_add + ra);
            }
#pragma unroll
            for (int nt = 0; nt < 8; nt++) {
                int pr = nt >> 1, ix = (nt & 1) * 2;
                MMA16816(sc[nt], qh4, kh4[pr][ix], kh4[pr][ix + 1]);
                MMA16816(sc[nt], qh4, kl4[pr][ix], kl4[pr][ix + 1]);
                MMA16816(sc[nt], ql4, kh4[pr][ix], kh4[pr][ix + 1]);
            }
        }

        if (j >= ntile - 2) {
            int row0 = q0 + wm * 16 + (lane >> 2);
#pragma unroll
            for (int nt = 0; nt < 8; nt++) {
                int col = j * 64 + nt * 8 + (lane & 3) * 2;
#pragma unroll
                for (int e = 0; e < 4; e++) {
                    int cc = col + (e & 1);
                    int rr = row0 + ((e >> 1) << 3);
                    if (cc > rr) sc[nt][e] = -1e30f;
                }
            }
        }

#pragma unroll
        for (int half = 0; half < 2; half++) {
            int e0 = half * 2;
            float mx = -1e30f;
#pragma unroll
            for (int nt = 0; nt < 8; nt++)
                mx = fmaxf(mx, fmaxf(sc[nt][e0], sc[nt][e0 + 1]));
            mx = fmaxf(mx, __shfl_xor_sync(0xffffffff, mx, 1));
            mx = fmaxf(mx, __shfl_xor_sync(0xffffffff, mx, 2));
            float mnew = fmaxf(mrow[half], mx);
            float alpha = __expf(mrow[half] - mnew);
            float sum = 0.f;
#pragma unroll
            for (int nt = 0; nt < 8; nt++) {
                float p0 = __expf(sc[nt][e0]     - mnew);
                float p1 = __expf(sc[nt][e0 + 1] - mnew);
                sc[nt][e0] = p0; sc[nt][e0 + 1] = p1;
                sum += p0 + p1;
            }
            sum += __shfl_xor_sync(0xffffffff, sum, 1);
            sum += __shfl_xor_sync(0xffffffff, sum, 2);
            lrow[half] = lrow[half] * alpha + sum;
            mrow[half] = mnew;
#pragma unroll
            for (int nt = 0; nt < 16; nt++) {
                oc[nt][e0]     *= alpha;
                oc[nt][e0 + 1] *= alpha;
            }
        }

#pragma unroll
        for (int kb2 = 0; kb2 < 4; kb2++) {
            int nt0 = kb2 * 2, nt1 = nt0 + 1;
            uint32_t ph[4], pl[4];
#pragma unroll
            for (int r4 = 0; r4 < 4; r4++) {
                int nts = (r4 >> 1) ? nt1 : nt0;
                int eb = (r4 & 1) * 2;
                float x0 = sc[nts][eb], x1 = sc[nts][eb + 1];
                __nv_bfloat16 h0 = __float2bfloat16(x0);
                __nv_bfloat16 h1 = __float2bfloat16(x1);
                ph[r4] = packbf2(h0, h1);
                pl[r4] = packbf2(__float2bfloat16(x0 - __bfloat162float(h0)),
                                 __float2bfloat16(x1 - __bfloat162float(h1)));
            }
            uint32_t vrow = kb2 * 16 * FSTR * 2;
#pragma unroll
            for (int np = 0; np < 8; np++) {
                uint32_t va = kvb + 2 * FTB + v_add + vrow + np * 32;
                uint32_t vb2 = va + FTB;
                uint32_t v4h[4], v4l[4];
                LDSM_X4T(v4h[0], v4h[1], v4h[2], v4h[3], va);
                LDSM_X4T(v4l[0], v4l[1], v4l[2], v4l[3], vb2);
                int nt = np * 2;
                MMA16816(oc[nt], ph, v4h[0], v4h[1]);
                MMA16816(oc[nt], ph, v4l[0], v4l[1]);
                MMA16816(oc[nt], pl, v4h[0], v4h[1]);
                MMA16816(oc[nt + 1], ph, v4h[2], v4h[3]);
                MMA16816(oc[nt + 1], ph, v4l[2], v4l[3]);
                MMA16816(oc[nt + 1], pl, v4h[2], v4h[3]);
            }
        }
    }

#pragma unroll
    for (int half = 0; half < 2; half++) {
        float inv_l = 1.0f / lrow[half];
        int row = q0 + wm * 16 + (lane >> 2) + half * 8;
        size_t ob = (((size_t)b * Tt + row) * Hh + h) * HD;
#pragma unroll
        for (int nt = 0; nt < 16; nt++) {
            int d = nt * 8 + (lane & 3) * 2;
            float v0 = oc[nt][half * 2] * inv_l;
            float v1 = oc[nt][half * 2 + 1] * inv_l;
            __nv_bfloat16 h0 = __float2bfloat16(v0);
            __nv_bfloat16 h1 = __float2bfloat16(v1);
            *(__nv_bfloat162*)&Oh[ob + d] = __nv_bfloat162(h0, h1);
            *(__nv_bfloat162*)&Ol[ob + d] = __nv_bfloat162(
                __float2bfloat16(v0 - __bfloat162float(h0)),
                __float2bfloat16(v1 - __bfloat162float(h1)));
        }
    }
}

// ---------------- launch ----------------
extern "C" void kernel_launch(void* const* d_in, const int* in_sizes, int n_in,
                              void* d_out, int out_size)
{
    const float* x  = (const float*)d_in[0];
    const float* Wq = (const float*)d_in[1];
    const float* Wk = (const float*)d_in[2];
    const float* Wv = (const float*)d_in[3];
    const float* Wo = (const float*)d_in[4];
    float* out = (float*)d_out;

    __nv_bfloat16 *xsh, *xsl, *osh, *osl, *wqkvh, *wqkvl, *woh, *wol;
    __nv_bfloat16 *qh, *ql, *kh, *kl, *vh, *vl;
    float2* rope;
    cudaGetSymbolAddress((void**)&xsh, g_xs_h);
    cudaGetSymbolAddress((void**)&xsl, g_xs_l);
    cudaGetSymbolAddress((void**)&osh, g_os_h);
    cudaGetSymbolAddress((void**)&osl, g_os_l);
    cudaGetSymbolAddress((void**)&wqkvh, g_wqkvt_h);
    cudaGetSymbolAddress((void**)&wqkvl, g_wqkvt_l);
    cudaGetSymbolAddress((void**)&woh, g_wot_h);
    cudaGetSymbolAddress((void**)&wol, g_wot_l);
    cudaGetSymbolAddress((void**)&qh, g_qh);
    cudaGetSymbolAddress((void**)&ql, g_ql);
    cudaGetSymbolAddress((void**)&kh, g_kh);
    cudaGetSymbolAddress((void**)&kl, g_kl);
    cudaGetSymbolAddress((void**)&vh, g_vh);
    cudaGetSymbolAddress((void**)&vl, g_vl);
    cudaGetSymbolAddress((void**)&rope, g_rope);

    const int M = Bsz * Tt;   // 4096
    const int n4 = M * Dd / 4;

    cudaFuncSetAttribute(mma_gemm, cudaFuncAttributeMaxDynamicSharedMemorySize, GEMM_SMEM);
    cudaFuncSetAttribute(flash_mma, cudaFuncAttributeMaxDynamicSharedMemorySize, FLASH_SMEM);

    // 1: all weight transposes+splits in one launch
    tsplit_all_kernel<<<dim3(64, 64, 4), dim3(32, 8)>>>(Wq, Wk, Wv, Wo, wqkvh, wqkvl, woh, wol);
    // 2: x split
    split_kernel<<<4096, 256>>>(x, xsh, xsl, n4);
    // 3: rope table
    rope_table_kernel<<<(Tt * 64) / 256, 256>>>(rope);
    // 4: fused QKV projection + RoPE + split + permute
    mma_gemm<<<dim3(NQKV / 128, M / 128), 256, GEMM_SMEM>>>(
        xsh, xsl, wqkvh, wqkvl, nullptr, M, NQKV, Dd, 1,
        rope, qh, ql, kh, kl, vh, vl);
    // 5: flash attention
    flash_mma<<<dim3(Tt / 128, Hh, Bsz), 256, FLASH_SMEM>>>(qh, ql, kh, kl, vh, vl, osh, osl);
    // 6: output projection -> d_out
    mma_gemm<<<dim3(Dd / 128, M / 128), 256, GEMM_SMEM>>>(
        osh, osl, woh, wol, out, M, Dd, Dd, 0,
        rope, qh, ql, kh, kl, vh, vl);
}